// round 5
// baseline (speedup 1.0000x reference)
#include <cuda_runtime.h>
#include <cuda_bf16.h>
#include <math.h>

// Problem constants (GRUObservationCell):
//   h[N=100000, HID=512], p[N, 128], X_obs[NOBS=50000, 64], M_obs[NOBS, 64],
//   i_obs[NOBS] (int32, sorted), w_prep[64,4,16], bias_prep[64,16],
//   weight_ih[1536,1024], weight_hh[1536,512], bias_ih[1536], bias_hh[1536]
// Output: h_new[N,512] then loss scalar (out_size = N*512 + 1).

#define HID 512
#define DD 64
#define PH 16
#define KI 1024          // D*PH
#define MAXROWS 50048    // 64-padded NOBS upper bound

// ---- device scratch (static allocation only; no cudaMalloc allowed) ----
__device__ float g_x[(size_t)MAXROWS * KI];       // prepped GRU input per obs row
__device__ int   g_crow[MAXROWS];                 // compacted obs-row indices (last occurrence)
__device__ int   g_cidx[MAXROWS];                 // corresponding h-row indices
__device__ int   g_count;                         // number of kept rows
__device__ float g_lossPartial[MAXROWS / 4];      // per-prep-block loss partials

// ---- helpers ----
__device__ __forceinline__ void fma2(unsigned long long &d,
                                     unsigned long long a,
                                     unsigned long long b) {
    // packed 2x fp32 FMA (Blackwell f32x2 pipe, 2x FFMA throughput)
    asm("fma.rn.f32x2 %0, %1, %2, %0;" : "+l"(d) : "l"(a), "l"(b));
}
__device__ __forceinline__ float lo32(unsigned long long v) {
    return __uint_as_float((unsigned)(v & 0xffffffffull));
}
__device__ __forceinline__ float hi32(unsigned long long v) {
    return __uint_as_float((unsigned)(v >> 32));
}
__device__ __forceinline__ float sigmoidf_(float x) {
    return 1.0f / (1.0f + expf(-x));
}

// ---- kernel 0: copy h -> out (h_new starts as h) ----
__global__ void copy_kernel(float4 *__restrict__ dst, const float4 *__restrict__ src, long n4) {
    long i = (long)blockIdx.x * blockDim.x + threadIdx.x;
    long stride = (long)gridDim.x * blockDim.x;
    for (; i < n4; i += stride) dst[i] = src[i];
}

// ---- kernel 1: reset compaction counter ----
__global__ void reset_kernel() {
    if (threadIdx.x == 0) g_count = 0;
}

// ---- kernel 2: compact last-occurrence rows (i_obs is sorted -> dups adjacent).
// CPU-XLA scatter applies updates in order, so the LAST duplicate wins.
__global__ void compact_kernel(const int *__restrict__ iobs, int nobs) {
    int r = blockIdx.x * blockDim.x + threadIdx.x;
    if (r >= nobs) return;
    int v = iobs[r];
    bool keep = (r == nobs - 1) || (iobs[r + 1] != v);
    if (keep) {
        int s = atomicAdd(&g_count, 1);   // order-free: each slot self-contained
        g_crow[s] = r;
        g_cidx[s] = v;
    }
}

// ---- kernel 3: prep features, GRU input x, per-block loss partials ----
// 256 threads = 4 rows x 64 d-lanes.
__global__ void prep_kernel(const float *__restrict__ p,
                            const float *__restrict__ X,
                            const float *__restrict__ Mm,
                            const int *__restrict__ iobs,
                            const float *__restrict__ wprep,
                            const float *__restrict__ bprep,
                            int nobs) {
    __shared__ float sw[DD * 64];   // w_prep [d][f][ph] flattened (4096)
    __shared__ float sb[DD * PH];   // bias_prep (1024)
    __shared__ float red[256];
    int tid = threadIdx.x;
    for (int k = tid; k < DD * 64; k += 256) sw[k] = wprep[k];
    for (int k = tid; k < DD * PH; k += 256) sb[k] = bprep[k];
    __syncthreads();

    int lrow = tid >> 6;
    int d = tid & 63;
    int row = blockIdx.x * 4 + lrow;
    float lossd = 0.0f;
    if (row < nobs) {
        int iidx = iobs[row];
        float mean = p[(size_t)iidx * 128 + d];
        float var  = fabsf(p[(size_t)iidx * 128 + 64 + d]) + 1e-6f;
        float xv   = X[(size_t)row * DD + d];
        float m    = Mm[(size_t)row * DD + d];
        float inv  = rsqrtf(var);
        float err  = (xv - mean) * inv;
        lossd = 0.5f * (err * err + logf(var)) * m;

        const float *w  = &sw[d * 64];
        const float *bb = &sb[d * PH];
        float4 *xo = reinterpret_cast<float4 *>(&g_x[(size_t)row * KI + d * PH]);
#pragma unroll
        for (int q = 0; q < 4; q++) {
            float4 o;
            float *op = reinterpret_cast<float *>(&o);
#pragma unroll
            for (int t = 0; t < 4; t++) {
                int ph = q * 4 + t;
                float v = xv * w[ph] + mean * w[16 + ph] + var * w[32 + ph] +
                          err * w[48 + ph] + bb[ph];
                op[t] = fmaxf(v, 0.0f) * m;
            }
            xo[q] = o;
        }
    }
    // deterministic block reduction of loss partial
    red[tid] = lossd;
    __syncthreads();
    for (int s = 128; s > 0; s >>= 1) {
        if (tid < s) red[tid] += red[tid + s];
        __syncthreads();
    }
    if (tid == 0) g_lossPartial[blockIdx.x] = red[0];
}

// ---- kernel 4: fused GRU gate GEMM + pointwise + scatter ----
// Block tile: BM=64 rows x BH=32 h-cols; computes all 6 gate dot-products
// (ir,iz,in over K=1024 ; hr,hz,hn over K=512), applies GRU pointwise in the
// epilogue, writes h_new rows directly into out.
#define BM 64
#define BH 32
#define KC 64
#define SST 66   // padded smem row stride (floats): conflict-free, 8B-aligned

__global__ __launch_bounds__(256, 2)
void gru_gemm_kernel(const float *__restrict__ h,
                     const float *__restrict__ Wih,
                     const float *__restrict__ Whh,
                     const float *__restrict__ bih,
                     const float *__restrict__ bhh,
                     float *__restrict__ out) {
    __shared__ __align__(16) float sA[BM * SST];   // x rows / h rows tile
    __shared__ __align__(16) float sB[96 * SST];   // 3 gates x 32 cols of W

    const int n_keep = g_count;
    const int rowbase = blockIdx.y * BM;
    if (rowbase >= n_keep) return;
    const int jb = blockIdx.x * BH;
    const int tid = threadIdx.x;
    const int tx = tid & 15;
    const int ty = tid >> 4;

    // packed accumulators (even/odd k lanes)
    unsigned long long accR[4][2]  = {};  // ir + hr
    unsigned long long accZ[4][2]  = {};  // iz + hz
    unsigned long long accIN[4][2] = {};  // inn (input side only)
    unsigned long long accHN[4][2] = {};  // hn  (hidden side only)

    // ---------------- phase 1: x @ Wih^T (K = 1024) ----------------
    for (int kt = 0; kt < KI; kt += KC) {
#pragma unroll
        for (int u = 0; u < 4; u++) {
            int idx = tid + 256 * u;          // 0..1023 float4 slots
            int r = idx >> 4, q = idx & 15;
            int slot = rowbase + r;
            float4 v = make_float4(0.f, 0.f, 0.f, 0.f);
            if (slot < n_keep) {
                int orow = g_crow[slot];
                v = *reinterpret_cast<const float4 *>(&g_x[(size_t)orow * KI + kt + q * 4]);
            }
            float *dst = &sA[r * SST + q * 4];
            dst[0] = v.x; dst[1] = v.y; dst[2] = v.z; dst[3] = v.w;
        }
#pragma unroll
        for (int u = 0; u < 6; u++) {
            int idx = tid + 256 * u;          // 0..1535
            int r = idx >> 4, q = idx & 15;   // r in 0..95
            int g = r >> 5, c = r & 31;
            int grow = jb + c + g * HID;
            float4 v = *reinterpret_cast<const float4 *>(&Wih[(size_t)grow * KI + kt + q * 4]);
            float *dst = &sB[r * SST + q * 4];
            dst[0] = v.x; dst[1] = v.y; dst[2] = v.z; dst[3] = v.w;
        }
        __syncthreads();
#pragma unroll
        for (int kk = 0; kk < KC; kk += 2) {
            unsigned long long a[4], b0[2], b1[2], b2[2];
#pragma unroll
            for (int i = 0; i < 4; i++)
                a[i] = *reinterpret_cast<const unsigned long long *>(&sA[(ty * 4 + i) * SST + kk]);
#pragma unroll
            for (int jj = 0; jj < 2; jj++) {
                int c = tx + jj * 16;
                b0[jj] = *reinterpret_cast<const unsigned long long *>(&sB[(c)         * SST + kk]);
                b1[jj] = *reinterpret_cast<const unsigned long long *>(&sB[(32 + c)    * SST + kk]);
                b2[jj] = *reinterpret_cast<const unsigned long long *>(&sB[(64 + c)    * SST + kk]);
            }
#pragma unroll
            for (int i = 0; i < 4; i++)
#pragma unroll
                for (int jj = 0; jj < 2; jj++) {
                    fma2(accR[i][jj],  a[i], b0[jj]);
                    fma2(accZ[i][jj],  a[i], b1[jj]);
                    fma2(accIN[i][jj], a[i], b2[jj]);
                }
        }
        __syncthreads();
    }

    // ---------------- phase 2: h_prev @ Whh^T (K = 512) ----------------
    for (int kt = 0; kt < HID; kt += KC) {
#pragma unroll
        for (int u = 0; u < 4; u++) {
            int idx = tid + 256 * u;
            int r = idx >> 4, q = idx & 15;
            int slot = rowbase + r;
            float4 v = make_float4(0.f, 0.f, 0.f, 0.f);
            if (slot < n_keep) {
                int hrow = g_cidx[slot];
                v = *reinterpret_cast<const float4 *>(&h[(size_t)hrow * HID + kt + q * 4]);
            }
            float *dst = &sA[r * SST + q * 4];
            dst[0] = v.x; dst[1] = v.y; dst[2] = v.z; dst[3] = v.w;
        }
#pragma unroll
        for (int u = 0; u < 6; u++) {
            int idx = tid + 256 * u;
            int r = idx >> 4, q = idx & 15;
            int g = r >> 5, c = r & 31;
            int grow = jb + c + g * HID;
            float4 v = *reinterpret_cast<const float4 *>(&Whh[(size_t)grow * HID + kt + q * 4]);
            float *dst = &sB[r * SST + q * 4];
            dst[0] = v.x; dst[1] = v.y; dst[2] = v.z; dst[3] = v.w;
        }
        __syncthreads();
#pragma unroll
        for (int kk = 0; kk < KC; kk += 2) {
            unsigned long long a[4], b0[2], b1[2], b2[2];
#pragma unroll
            for (int i = 0; i < 4; i++)
                a[i] = *reinterpret_cast<const unsigned long long *>(&sA[(ty * 4 + i) * SST + kk]);
#pragma unroll
            for (int jj = 0; jj < 2; jj++) {
                int c = tx + jj * 16;
                b0[jj] = *reinterpret_cast<const unsigned long long *>(&sB[(c)      * SST + kk]);
                b1[jj] = *reinterpret_cast<const unsigned long long *>(&sB[(32 + c) * SST + kk]);
                b2[jj] = *reinterpret_cast<const unsigned long long *>(&sB[(64 + c) * SST + kk]);
            }
#pragma unroll
            for (int i = 0; i < 4; i++)
#pragma unroll
                for (int jj = 0; jj < 2; jj++) {
                    fma2(accR[i][jj],  a[i], b0[jj]);
                    fma2(accZ[i][jj],  a[i], b1[jj]);
                    fma2(accHN[i][jj], a[i], b2[jj]);
                }
        }
        __syncthreads();
    }

    // ---------------- epilogue: GRU pointwise + scatter ----------------
#pragma unroll
    for (int jj = 0; jj < 2; jj++) {
        int j = jb + tx + jj * 16;
        float br = bih[j] + bhh[j];
        float bz = bih[j + HID] + bhh[j + HID];
        float bni = bih[j + 2 * HID];
        float bnh = bhh[j + 2 * HID];
#pragma unroll
        for (int i = 0; i < 4; i++) {
            int slot = rowbase + ty * 4 + i;
            if (slot >= n_keep) continue;
            int hrow = g_cidx[slot];
            float sr = lo32(accR[i][jj])  + hi32(accR[i][jj])  + br;
            float sz = lo32(accZ[i][jj])  + hi32(accZ[i][jj])  + bz;
            float si = lo32(accIN[i][jj]) + hi32(accIN[i][jj]) + bni;
            float sh = lo32(accHN[i][jj]) + hi32(accHN[i][jj]) + bnh;
            float r = sigmoidf_(sr);
            float z = sigmoidf_(sz);
            float n = tanhf(si + r * sh);
            float hp = h[(size_t)hrow * HID + j];
            out[(size_t)hrow * HID + j] = (1.0f - z) * n + z * hp;
        }
    }
}

// ---- kernel 5: deterministic final loss reduction ----
__global__ void loss_final_kernel(float *__restrict__ out, int nPart, long pos) {
    __shared__ float red[256];
    float s = 0.0f;
    for (int k = threadIdx.x; k < nPart; k += 256) s += g_lossPartial[k];
    red[threadIdx.x] = s;
    __syncthreads();
    for (int t = 128; t > 0; t >>= 1) {
        if (threadIdx.x < t) red[threadIdx.x] += red[threadIdx.x + t];
        __syncthreads();
    }
    if (threadIdx.x == 0) out[pos] = red[0];
}

// ---- launch ----
extern "C" void kernel_launch(void *const *d_in, const int *in_sizes, int n_in,
                              void *d_out, int out_size) {
    const float *h     = (const float *)d_in[0];
    const float *p     = (const float *)d_in[1];
    const float *X     = (const float *)d_in[2];
    const float *M     = (const float *)d_in[3];
    const int   *iobs  = (const int *)d_in[4];
    const float *wprep = (const float *)d_in[5];
    const float *bprep = (const float *)d_in[6];
    const float *wih   = (const float *)d_in[7];
    const float *whh   = (const float *)d_in[8];
    const float *bih   = (const float *)d_in[9];
    const float *bhh   = (const float *)d_in[10];

    int Nh   = in_sizes[0] / HID;   // 100000
    int nobs = in_sizes[4];         // 50000

    float *out = (float *)d_out;
    long n4 = (long)Nh * HID / 4;

    copy_kernel<<<2048, 256>>>((float4 *)out, (const float4 *)h, n4);
    reset_kernel<<<1, 1>>>();
    compact_kernel<<<(nobs + 255) / 256, 256>>>(iobs, nobs);
    int nPrep = (nobs + 3) / 4;
    prep_kernel<<<nPrep, 256>>>(p, X, M, iobs, wprep, bprep, nobs);
    dim3 grid(HID / BH, (nobs + BM - 1) / BM);   // 16 x 782 (worst case: no dups)
    gru_gemm_kernel<<<grid, 256>>>(h, wih, whh, bih, bhh, out);
    if ((long)out_size > (long)Nh * HID)
        loss_final_kernel<<<1, 256>>>(out, nPrep, (long)out_size - 1);
}

// round 9
// speedup vs baseline: 1.9375x; 1.9375x over previous
#include <cuda_runtime.h>
#include <cuda_bf16.h>
#include <math.h>
#include <stdint.h>

// GRUObservationCell on GB300 — mma.sync bf16-split GEMM (no 'a'-arch features:
// harness PTX target is sm_103, so tcgen05 is unavailable; mma.sync.m16n8k16 is
// baseline PTX and runs on the tensor pipes).
//   h[N=100000,512], p[N,128], X_obs[50000,64], M_obs[50000,64],
//   i_obs[50000] sorted int32, w_prep[64,4,16], bias_prep[64,16],
//   weight_ih[1536,1024], weight_hh[1536,512], bias_ih[1536], bias_hh[1536]
// out = h_new[N,512] ++ loss scalar.

#define HID 512
#define DD 64
#define PH 16
#define KTOT 1536            // unified K: 0..1023 = x@Wih, 1024..1535 = h@Whh
#define NCHUNK 24            // 1536 / 64
#define KCH 64
#define MAXROWS 50176

// ---------- static device scratch ----------
__device__ __nv_bfloat16 g_Ahi[(size_t)MAXROWS * KTOT];
__device__ __nv_bfloat16 g_Alo[(size_t)MAXROWS * KTOT];
__device__ __nv_bfloat16 g_Bhi[(size_t)KTOT * KTOT];
__device__ __nv_bfloat16 g_Blo[(size_t)KTOT * KTOT];
__device__ float g_lossPartial[MAXROWS / 4];

// ---------- helpers ----------
__device__ __forceinline__ uint32_t smem_u32(const void *p) {
    uint32_t a;
    asm("{ .reg .u64 t; cvta.to.shared.u64 t, %1; cvt.u32.u64 %0, t; }" : "=r"(a) : "l"(p));
    return a;
}
__device__ __forceinline__ void cpasync16(uint32_t dst, const void *src) {
    asm volatile("cp.async.cg.shared.global [%0], [%1], 16;" :: "r"(dst), "l"(src));
}
__device__ __forceinline__ void mma_bf16(float (&d)[4], const uint32_t (&a)[4],
                                         const uint32_t (&b)[2]) {
    asm volatile(
        "mma.sync.aligned.m16n8k16.row.col.f32.bf16.bf16.f32 "
        "{%0,%1,%2,%3}, {%4,%5,%6,%7}, {%8,%9}, {%0,%1,%2,%3};"
        : "+f"(d[0]), "+f"(d[1]), "+f"(d[2]), "+f"(d[3])
        : "r"(a[0]), "r"(a[1]), "r"(a[2]), "r"(a[3]), "r"(b[0]), "r"(b[1]));
}
__device__ __forceinline__ void f2bfs(float v, __nv_bfloat16 &hi, __nv_bfloat16 &lo) {
    hi = __float2bfloat16_rn(v);
    lo = __float2bfloat16_rn(v - __bfloat162float(hi));
}

// ---------- kernel: h_new = h (bulk copy) ----------
__global__ void copy_kernel(float4 *__restrict__ dst, const float4 *__restrict__ src, long n4) {
    long i = (long)blockIdx.x * blockDim.x + threadIdx.x;
    long st = (long)gridDim.x * blockDim.x;
    for (; i < n4; i += st) dst[i] = src[i];
}

// ---------- prep: features -> bf16 hi/lo A-planes (k 0..1023), loss partials ----------
__global__ void prep_kernel(const float *__restrict__ p, const float *__restrict__ X,
                            const float *__restrict__ Mm, const int *__restrict__ iobs,
                            const float *__restrict__ wprep, const float *__restrict__ bprep,
                            int nobs) {
    __shared__ float swt[64 * 64];   // transposed: [f*16+ph][d]
    __shared__ float sbt[16 * 64];   // [ph][d]
    __shared__ float red[256];
    int tid = threadIdx.x;
    for (int k = tid; k < 4096; k += 256) swt[(k & 63) * 64 + (k >> 6)] = wprep[k];
    for (int k = tid; k < 1024; k += 256) sbt[(k & 15) * 64 + (k >> 4)] = bprep[k];
    __syncthreads();

    int d = tid & 63;
    int row = blockIdx.x * 4 + (tid >> 6);
    float lossd = 0.0f;
    if (row < nobs) {
        int iidx = iobs[row];
        float mean = p[(size_t)iidx * 128 + d];
        float var  = fabsf(p[(size_t)iidx * 128 + 64 + d]) + 1e-6f;
        float xv   = X[(size_t)row * DD + d];
        float m    = Mm[(size_t)row * DD + d];
        float err  = (xv - mean) * rsqrtf(var);
        lossd = 0.5f * (err * err + logf(var)) * m;

        __nv_bfloat16 oh[16], ol[16];
#pragma unroll
        for (int ph = 0; ph < PH; ph++) {
            float v = xv * swt[ph * 64 + d] + mean * swt[(16 + ph) * 64 + d] +
                      var * swt[(32 + ph) * 64 + d] + err * swt[(48 + ph) * 64 + d] +
                      sbt[ph * 64 + d];
            f2bfs(fmaxf(v, 0.0f) * m, oh[ph], ol[ph]);
        }
        uint4 *ph4 = reinterpret_cast<uint4 *>(oh);
        uint4 *pl4 = reinterpret_cast<uint4 *>(ol);
        uint4 *dh = reinterpret_cast<uint4 *>(&g_Ahi[(size_t)row * KTOT + d * PH]);
        uint4 *dl = reinterpret_cast<uint4 *>(&g_Alo[(size_t)row * KTOT + d * PH]);
        dh[0] = ph4[0]; dh[1] = ph4[1];
        dl[0] = pl4[0]; dl[1] = pl4[1];
    }
    red[tid] = lossd;
    __syncthreads();
    for (int s = 128; s > 0; s >>= 1) {
        if (tid < s) red[tid] += red[tid + s];
        __syncthreads();
    }
    if (tid == 0) g_lossPartial[blockIdx.x] = red[0];
}

// ---------- gather h rows -> A-plane cols 1024..1535 ----------
__global__ void hconv_kernel(const float *__restrict__ h, const int *__restrict__ iobs, int nobs) {
    long idx = (long)blockIdx.x * 256 + threadIdx.x;  // over nobs*128 float4 units
    if (idx >= (long)nobs * 128) return;
    int r = (int)(idx >> 7), q = (int)(idx & 127);
    int hrow = iobs[r];
    float4 v = *reinterpret_cast<const float4 *>(&h[(size_t)hrow * HID + q * 4]);
    __nv_bfloat16 oh[4], ol[4];
    f2bfs(v.x, oh[0], ol[0]); f2bfs(v.y, oh[1], ol[1]);
    f2bfs(v.z, oh[2], ol[2]); f2bfs(v.w, oh[3], ol[3]);
    *reinterpret_cast<uint2 *>(&g_Ahi[(size_t)r * KTOT + 1024 + q * 4]) =
        *reinterpret_cast<uint2 *>(oh);
    *reinterpret_cast<uint2 *>(&g_Alo[(size_t)r * KTOT + 1024 + q * 4]) =
        *reinterpret_cast<uint2 *>(ol);
}

// ---------- weights -> bf16 hi/lo B-planes [1536 gates][1536 k] ----------
__global__ void wconv_kernel(const float *__restrict__ wih, const float *__restrict__ whh) {
    int idx = blockIdx.x * 256 + threadIdx.x;  // over 1536*384 float4 units
    if (idx >= KTOT * 384) return;
    int g = idx / 384, q = idx - g * 384;
    int k = q * 4;
    float4 v = (k < 1024)
                   ? *reinterpret_cast<const float4 *>(&wih[(size_t)g * 1024 + k])
                   : *reinterpret_cast<const float4 *>(&whh[(size_t)g * 512 + (k - 1024)]);
    __nv_bfloat16 oh[4], ol[4];
    f2bfs(v.x, oh[0], ol[0]); f2bfs(v.y, oh[1], ol[1]);
    f2bfs(v.z, oh[2], ol[2]); f2bfs(v.w, oh[3], ol[3]);
    *reinterpret_cast<uint2 *>(&g_Bhi[(size_t)g * KTOT + k]) = *reinterpret_cast<uint2 *>(oh);
    *reinterpret_cast<uint2 *>(&g_Blo[(size_t)g * KTOT + k]) = *reinterpret_cast<uint2 *>(ol);
}

// ---------- main MMA GEMM + GRU epilogue ----------
// smem stage (row stride 144B = 72 bf16, conflict-free for frag pattern):
//   Ahi 128x144 = 18432 | Alo 18432 | Bhi 192x144 = 27648 | Blo 27648
#define A_STRIDE 144
#define SA_HI 0
#define SA_LO 18432
#define SB_HI 36864
#define SB_LO 64512
#define STAGE 92160
#define GEMM_SMEM (2 * STAGE)   // 184320

__device__ __forceinline__ void load_chunk(int c, char *stb, int rowbase, int jb, int tid) {
    size_t kof = (size_t)c * KCH;
#pragma unroll
    for (int u = 0; u < 8; u++) {            // A: 2 planes x 128 rows x 8 granules
        int idx = tid + u * 256;
        int var = idx >> 10;
        int r = (idx >> 3) & 127;
        int gq = idx & 7;
        const __nv_bfloat16 *sp = var ? g_Alo : g_Ahi;
        cpasync16(smem_u32(stb + (var ? SA_LO : SA_HI) + r * A_STRIDE + gq * 16),
                  sp + (size_t)(rowbase + r) * KTOT + kof + gq * 8);
    }
#pragma unroll
    for (int u = 0; u < 12; u++) {           // B: 2 planes x 192 rows x 8 granules
        int idx = tid + u * 256;
        int var = idx >= 1536;
        int i2 = idx - (var ? 1536 : 0);
        int r = i2 >> 3, gq = i2 & 7;
        int grow = (r >> 6) * HID + jb + (r & 63);   // gate*512 + jb + jr
        const __nv_bfloat16 *sp = var ? g_Blo : g_Bhi;
        cpasync16(smem_u32(stb + (var ? SB_LO : SB_HI) + r * A_STRIDE + gq * 16),
                  sp + (size_t)grow * KTOT + kof + gq * 8);
    }
}

#define LDS32(base, off) (*reinterpret_cast<const uint32_t *>((base) + (off)))

// One K-chunk of MMAs. ACCN = accNI (chunks 0..15) or accNH (16..23).
#define COMPUTE_CHUNK(stb, ACCN)                                                        \
    do {                                                                                \
        _Pragma("unroll")                                                               \
        for (int kk = 0; kk < 4; kk++) {                                                \
            int kbyte = (kk * 16 + t * 2) * 2;                                          \
            uint32_t ah[4][4], al[4][4];                                                \
            _Pragma("unroll")                                                           \
            for (int mt = 0; mt < 4; mt++) {                                            \
                int ro = (mg * 64 + mt * 16 + g) * A_STRIDE + kbyte;                    \
                ah[mt][0] = LDS32(stb + SA_HI, ro);                                     \
                ah[mt][1] = LDS32(stb + SA_HI, ro + 8 * A_STRIDE);                      \
                ah[mt][2] = LDS32(stb + SA_HI, ro + 16);                                \
                ah[mt][3] = LDS32(stb + SA_HI, ro + 8 * A_STRIDE + 16);                 \
                al[mt][0] = LDS32(stb + SA_LO, ro);                                     \
                al[mt][1] = LDS32(stb + SA_LO, ro + 8 * A_STRIDE);                      \
                al[mt][2] = LDS32(stb + SA_LO, ro + 16);                                \
                al[mt][3] = LDS32(stb + SA_LO, ro + 8 * A_STRIDE + 16);                 \
            }                                                                           \
            _Pragma("unroll")                                                           \
            for (int jt = 0; jt < 2; jt++) {                                            \
                int nro0 = (jg * 16 + jt * 8 + g) * A_STRIDE + kbyte;                   \
                /* set 0: r-gate (B rows 0..63) */                                      \
                {                                                                       \
                    uint32_t bh[2] = {LDS32(stb + SB_HI, nro0),                         \
                                      LDS32(stb + SB_HI, nro0 + 16)};                   \
                    uint32_t bl[2] = {LDS32(stb + SB_LO, nro0),                         \
                                      LDS32(stb + SB_LO, nro0 + 16)};                   \
                    _Pragma("unroll")                                                   \
                    for (int mt = 0; mt < 4; mt++) {                                    \
                        mma_bf16(accR[mt][jt], ah[mt], bh);                             \
                        mma_bf16(accR[mt][jt], al[mt], bh);                             \
                        mma_bf16(accR[mt][jt], ah[mt], bl);                             \
                    }                                                                   \
                }                                                                       \
                /* set 1: z-gate (B rows 64..127) */                                    \
                {                                                                       \
                    int nro = nro0 + 64 * A_STRIDE;                                     \
                    uint32_t bh[2] = {LDS32(stb + SB_HI, nro),                          \
                                      LDS32(stb + SB_HI, nro + 16)};                    \
                    uint32_t bl[2] = {LDS32(stb + SB_LO, nro),                          \
                                      LDS32(stb + SB_LO, nro + 16)};                    \
                    _Pragma("unroll")                                                   \
                    for (int mt = 0; mt < 4; mt++) {                                    \
                        mma_bf16(accZ[mt][jt], ah[mt], bh);                             \
                        mma_bf16(accZ[mt][jt], al[mt], bh);                             \
                        mma_bf16(accZ[mt][jt], ah[mt], bl);                             \
                    }                                                                   \
                }                                                                       \
                /* set 2: n-gate (B rows 128..191) */                                   \
                {                                                                       \
                    int nro = nro0 + 128 * A_STRIDE;                                    \
                    uint32_t bh[2] = {LDS32(stb + SB_HI, nro),                          \
                                      LDS32(stb + SB_HI, nro + 16)};                    \
                    uint32_t bl[2] = {LDS32(stb + SB_LO, nro),                          \
                                      LDS32(stb + SB_LO, nro + 16)};                    \
                    _Pragma("unroll")                                                   \
                    for (int mt = 0; mt < 4; mt++) {                                    \
                        mma_bf16(ACCN[mt][jt], ah[mt], bh);                             \
                        mma_bf16(ACCN[mt][jt], al[mt], bh);                             \
                        mma_bf16(ACCN[mt][jt], ah[mt], bl);                             \
                    }                                                                   \
                }                                                                       \
            }                                                                           \
        }                                                                               \
    } while (0)

__global__ __launch_bounds__(256, 1)
void gru_mma_kernel(const float *__restrict__ h, const int *__restrict__ iobs,
                    const float *__restrict__ bih, const float *__restrict__ bhh,
                    float *__restrict__ out, int nobs) {
    extern __shared__ char smem[];
    int tid = threadIdx.x, wid = tid >> 5, lane = tid & 31;
    int mg = wid >> 2, jg = wid & 3;          // 2 M-groups x 4 J-groups
    int g = lane >> 2, t = lane & 3;
    int rowbase = blockIdx.y * 128;
    int jb = blockIdx.x * 64;

    float accR[4][2][4] = {}, accZ[4][2][4] = {};
    float accNI[4][2][4] = {}, accNH[4][2][4] = {};

    char *st0 = smem, *st1 = smem + STAGE;
    load_chunk(0, st0, rowbase, jb, tid);
    asm volatile("cp.async.commit_group;" ::: "memory");
    load_chunk(1, st1, rowbase, jb, tid);
    asm volatile("cp.async.commit_group;" ::: "memory");

    for (int c = 0; c < NCHUNK; c++) {
        char *stb = (c & 1) ? st1 : st0;
        asm volatile("cp.async.wait_group 1;" ::: "memory");
        __syncthreads();
        if (c < 16) COMPUTE_CHUNK(stb, accNI);
        else        COMPUTE_CHUNK(stb, accNH);
        __syncthreads();
        if (c + 2 < NCHUNK) {
            load_chunk(c + 2, stb, rowbase, jb, tid);
            asm volatile("cp.async.commit_group;" ::: "memory");
        }
    }

    // ---- epilogue: GRU pointwise + last-occurrence scatter (all thread-local)
#pragma unroll
    for (int mt = 0; mt < 4; mt++) {
#pragma unroll
        for (int h2 = 0; h2 < 2; h2++) {
            int slot = rowbase + mg * 64 + mt * 16 + g + h2 * 8;
            bool kept = false;
            int hrow = 0;
            if (slot < nobs) {
                hrow = iobs[slot];
                kept = (slot == nobs - 1) || (iobs[slot + 1] != hrow);
            }
            if (kept) {
#pragma unroll
                for (int jt = 0; jt < 2; jt++) {
#pragma unroll
                    for (int ec = 0; ec < 2; ec++) {
                        int e = h2 * 2 + ec;
                        int j = jb + jg * 16 + jt * 8 + t * 2 + ec;
                        float sr = accR[mt][jt][e] + bih[j] + bhh[j];
                        float sz = accZ[mt][jt][e] + bih[HID + j] + bhh[HID + j];
                        float si = accNI[mt][jt][e] + bih[2 * HID + j];
                        float sh = accNH[mt][jt][e] + bhh[2 * HID + j];
                        float r = 1.0f / (1.0f + expf(-sr));
                        float z = 1.0f / (1.0f + expf(-sz));
                        float n = tanhf(si + r * sh);
                        float hp = h[(size_t)hrow * HID + j];
                        out[(size_t)hrow * HID + j] = (1.0f - z) * n + z * hp;
                    }
                }
            }
        }
    }
}

// ---------- final loss reduction ----------
__global__ void loss_final_kernel(float *__restrict__ out, int nPart, long pos) {
    __shared__ float red[256];
    float s = 0.0f;
    for (int k = threadIdx.x; k < nPart; k += 256) s += g_lossPartial[k];
    red[threadIdx.x] = s;
    __syncthreads();
    for (int t = 128; t > 0; t >>= 1) {
        if (threadIdx.x < t) red[threadIdx.x] += red[threadIdx.x + t];
        __syncthreads();
    }
    if (threadIdx.x == 0) out[pos] = red[0];
}

// ---------- launch ----------
extern "C" void kernel_launch(void *const *d_in, const int *in_sizes, int n_in,
                              void *d_out, int out_size) {
    const float *h     = (const float *)d_in[0];
    const float *p     = (const float *)d_in[1];
    const float *X     = (const float *)d_in[2];
    const float *M     = (const float *)d_in[3];
    const int   *iobs  = (const int *)d_in[4];
    const float *wprep = (const float *)d_in[5];
    const float *bprep = (const float *)d_in[6];
    const float *wih   = (const float *)d_in[7];
    const float *whh   = (const float *)d_in[8];
    const float *bih   = (const float *)d_in[9];
    const float *bhh   = (const float *)d_in[10];

    int Nh = in_sizes[0] / HID;    // 100000
    int nobs = in_sizes[4];        // 50000
    float *out = (float *)d_out;

    cudaFuncSetAttribute(gru_mma_kernel, cudaFuncAttributeMaxDynamicSharedMemorySize,
                         GEMM_SMEM);

    long n4 = (long)Nh * HID / 4;
    copy_kernel<<<2048, 256>>>((float4 *)out, (const float4 *)h, n4);

    int nPrep = (nobs + 3) / 4;
    prep_kernel<<<nPrep, 256>>>(p, X, M, iobs, wprep, bprep, nobs);
    hconv_kernel<<<(int)(((long)nobs * 128 + 255) / 256), 256>>>(h, iobs, nobs);
    wconv_kernel<<<(KTOT * 384 + 255) / 256, 256>>>(wih, whh);

    dim3 grid(HID / 64, (nobs + 127) / 128);   // 8 x 391
    gru_mma_kernel<<<grid, 256, GEMM_SMEM>>>(h, iobs, bih, bhh, out, nobs);

    if ((long)out_size > (long)Nh * HID)
        loss_final_kernel<<<1, 256>>>(out, nPrep, (long)out_size - 1);
}

// round 11
// speedup vs baseline: 3.0423x; 1.5702x over previous
#include <cuda_runtime.h>
#include <cuda_fp16.h>
#include <math.h>
#include <stdint.h>

// GRUObservationCell on GB300 — mma.sync fp16 A-split GEMM + row dedup.
// (harness PTX target is sm_103: no tcgen05; mma.sync.m16n8k16 is baseline PTX)
//   h[N=100000,512], p[N,128], X_obs[50000,64], M_obs[50000,64],
//   i_obs[50000] sorted int32, w_prep[64,4,16], bias_prep[64,16],
//   weight_ih[1536,1024], weight_hh[1536,512], bias_ih[1536], bias_hh[1536]
// out = h_new[N,512] ++ loss scalar.
//
// Math: gates = [x|h] @ [Wih|Whh]^T over unified K=1536. A split into fp16
// hi+lo planes (A exact to ~2^-22); B single fp16 plane (error A·(B-fp16(B))
// ~1.4e-4 rel). 2 MMA terms per tile instead of 3x bf16. Duplicate i_obs rows
// (last occurrence wins) compacted out of the GEMM.

#define HID 512
#define DD 64
#define PH 16
#define KTOT 1536
#define NCHUNK 24
#define KCH 64
#define MAXROWS 50176

// ---------- static device scratch ----------
__device__ __half g_Ah[(size_t)MAXROWS * KTOT];
__device__ __half g_Al[(size_t)MAXROWS * KTOT];
__device__ __half g_Bh[(size_t)KTOT * KTOT];
__device__ int   g_crow[MAXROWS];
__device__ int   g_cidx[MAXROWS];
__device__ int   g_count;
__device__ float g_lossPartial[MAXROWS / 4];

// ---------- helpers ----------
__device__ __forceinline__ uint32_t smem_u32(const void *p) {
    uint32_t a;
    asm("{ .reg .u64 t; cvta.to.shared.u64 t, %1; cvt.u32.u64 %0, t; }" : "=r"(a) : "l"(p));
    return a;
}
__device__ __forceinline__ void cpasync16(uint32_t dst, const void *src) {
    asm volatile("cp.async.cg.shared.global [%0], [%1], 16;" :: "r"(dst), "l"(src));
}
__device__ __forceinline__ void mma_fp16(float (&d)[4], const uint32_t (&a)[4],
                                         const uint32_t (&b)[2]) {
    asm volatile(
        "mma.sync.aligned.m16n8k16.row.col.f32.f16.f16.f32 "
        "{%0,%1,%2,%3}, {%4,%5,%6,%7}, {%8,%9}, {%0,%1,%2,%3};"
        : "+f"(d[0]), "+f"(d[1]), "+f"(d[2]), "+f"(d[3])
        : "r"(a[0]), "r"(a[1]), "r"(a[2]), "r"(a[3]), "r"(b[0]), "r"(b[1]));
}
__device__ __forceinline__ void f2hs(float v, __half &hi, __half &lo) {
    hi = __float2half_rn(v);
    lo = __float2half_rn(v - __half2float(hi));
}

// ---------- h_new = h (bulk copy) ----------
__global__ void copy_kernel(float4 *__restrict__ dst, const float4 *__restrict__ src, long n4) {
    long i = (long)blockIdx.x * blockDim.x + threadIdx.x;
    long st = (long)gridDim.x * blockDim.x;
    for (; i < n4; i += st) dst[i] = src[i];
}

// ---------- compaction: last occurrence of each sorted i_obs value ----------
__global__ void reset_kernel() {
    if (threadIdx.x == 0) g_count = 0;
}
__global__ void compact_kernel(const int *__restrict__ iobs, int nobs) {
    int r = blockIdx.x * blockDim.x + threadIdx.x;
    if (r >= nobs) return;
    int v = iobs[r];
    bool keep = (r == nobs - 1) || (iobs[r + 1] != v);   // last occurrence wins
    if (keep) {
        int s = atomicAdd(&g_count, 1);   // unordered slots; each self-contained
        g_crow[s] = r;
        g_cidx[s] = v;
    }
}

// ---------- prep: features -> fp16 hi/lo A-planes (k 0..1023), loss partials ----------
__global__ void prep_kernel(const float *__restrict__ p, const float *__restrict__ X,
                            const float *__restrict__ Mm, const int *__restrict__ iobs,
                            const float *__restrict__ wprep, const float *__restrict__ bprep,
                            int nobs) {
    __shared__ float swt[64 * 64];   // transposed: [f*16+ph][d]
    __shared__ float sbt[16 * 64];   // [ph][d]
    __shared__ float red[256];
    int tid = threadIdx.x;
    for (int k = tid; k < 4096; k += 256) swt[(k & 63) * 64 + (k >> 6)] = wprep[k];
    for (int k = tid; k < 1024; k += 256) sbt[(k & 15) * 64 + (k >> 4)] = bprep[k];
    __syncthreads();

    int d = tid & 63;
    int row = blockIdx.x * 4 + (tid >> 6);
    float lossd = 0.0f;
    if (row < nobs) {
        int iidx = iobs[row];
        float mean = p[(size_t)iidx * 128 + d];
        float var  = fabsf(p[(size_t)iidx * 128 + 64 + d]) + 1e-6f;
        float xv   = X[(size_t)row * DD + d];
        float m    = Mm[(size_t)row * DD + d];
        float err  = (xv - mean) * rsqrtf(var);
        lossd = 0.5f * (err * err + logf(var)) * m;

        __half oh[16], ol[16];
#pragma unroll
        for (int ph = 0; ph < PH; ph++) {
            float v = xv * swt[ph * 64 + d] + mean * swt[(16 + ph) * 64 + d] +
                      var * swt[(32 + ph) * 64 + d] + err * swt[(48 + ph) * 64 + d] +
                      sbt[ph * 64 + d];
            f2hs(fmaxf(v, 0.0f) * m, oh[ph], ol[ph]);
        }
        uint4 *ph4 = reinterpret_cast<uint4 *>(oh);
        uint4 *pl4 = reinterpret_cast<uint4 *>(ol);
        uint4 *dh = reinterpret_cast<uint4 *>(&g_Ah[(size_t)row * KTOT + d * PH]);
        uint4 *dl = reinterpret_cast<uint4 *>(&g_Al[(size_t)row * KTOT + d * PH]);
        dh[0] = ph4[0]; dh[1] = ph4[1];
        dl[0] = pl4[0]; dl[1] = pl4[1];
    }
    red[tid] = lossd;
    __syncthreads();
    for (int s = 128; s > 0; s >>= 1) {
        if (tid < s) red[tid] += red[tid + s];
        __syncthreads();
    }
    if (tid == 0) g_lossPartial[blockIdx.x] = red[0];
}

// ---------- gather h rows (kept only) -> A-plane cols 1024..1535 ----------
__global__ void hconv_kernel(const float *__restrict__ h, int nobs) {
    long idx = (long)blockIdx.x * 256 + threadIdx.x;  // slot*128 + q
    int slot = (int)(idx >> 7);
    if (slot >= g_count) return;
    int q = (int)(idx & 127);
    int r = g_crow[slot];
    int hrow = g_cidx[slot];
    float4 v = *reinterpret_cast<const float4 *>(&h[(size_t)hrow * HID + q * 4]);
    __half oh[4], ol[4];
    f2hs(v.x, oh[0], ol[0]); f2hs(v.y, oh[1], ol[1]);
    f2hs(v.z, oh[2], ol[2]); f2hs(v.w, oh[3], ol[3]);
    *reinterpret_cast<uint2 *>(&g_Ah[(size_t)r * KTOT + 1024 + q * 4]) =
        *reinterpret_cast<uint2 *>(oh);
    *reinterpret_cast<uint2 *>(&g_Al[(size_t)r * KTOT + 1024 + q * 4]) =
        *reinterpret_cast<uint2 *>(ol);
}

// ---------- weights -> single fp16 B-plane [1536 gates][1536 k] ----------
__global__ void wconv_kernel(const float *__restrict__ wih, const float *__restrict__ whh) {
    int idx = blockIdx.x * 256 + threadIdx.x;  // over 1536*384 float4 units
    if (idx >= KTOT * 384) return;
    int g = idx / 384, q = idx - g * 384;
    int k = q * 4;
    float4 v = (k < 1024)
                   ? *reinterpret_cast<const float4 *>(&wih[(size_t)g * 1024 + k])
                   : *reinterpret_cast<const float4 *>(&whh[(size_t)g * 512 + (k - 1024)]);
    __half o[4];
    o[0] = __float2half_rn(v.x); o[1] = __float2half_rn(v.y);
    o[2] = __float2half_rn(v.z); o[3] = __float2half_rn(v.w);
    *reinterpret_cast<uint2 *>(&g_Bh[(size_t)g * KTOT + k]) = *reinterpret_cast<uint2 *>(o);
}

// ---------- main MMA GEMM + GRU epilogue ----------
// smem stage (row stride 144B, conflict-free for the fragment pattern):
//   Ahi 128x144 = 18432 | Alo 18432 | B 192x144 = 27648   -> 64512/stage
#define A_STRIDE 144
#define SA_HI 0
#define SA_LO 18432
#define SB    36864
#define STAGE 64512
#define GEMM_SMEM (2 * STAGE)   // 129024

__device__ __forceinline__ void load_chunk(int c, char *stb, const int *srows, int jb,
                                           int tid) {
    size_t kof = (size_t)c * KCH;
#pragma unroll
    for (int u = 0; u < 8; u++) {            // A: 2 planes x 128 rows x 8 granules
        int idx = tid + u * 256;
        int var = idx >> 10;
        int r = (idx >> 3) & 127;
        int gq = idx & 7;
        const __half *sp = var ? g_Al : g_Ah;
        cpasync16(smem_u32(stb + (var ? SA_LO : SA_HI) + r * A_STRIDE + gq * 16),
                  sp + (size_t)srows[r] * KTOT + kof + gq * 8);
    }
#pragma unroll
    for (int u = 0; u < 6; u++) {            // B: 192 rows x 8 granules
        int idx = tid + u * 256;
        int r = idx >> 3, gq = idx & 7;
        int grow = (r >> 6) * HID + jb + (r & 63);   // gate*512 + jb + jr
        cpasync16(smem_u32(stb + SB + r * A_STRIDE + gq * 16),
                  g_Bh + (size_t)grow * KTOT + kof + gq * 8);
    }
}

#define LDS32(base, off) (*reinterpret_cast<const uint32_t *>((base) + (off)))

// One K-chunk of MMAs (2 terms: Ahi*B + Alo*B). ACCN = accNI (c<16) or accNH.
#define COMPUTE_CHUNK(stb, ACCN)                                                        \
    do {                                                                                \
        _Pragma("unroll")                                                               \
        for (int kk = 0; kk < 4; kk++) {                                                \
            int kbyte = (kk * 16 + t * 2) * 2;                                          \
            uint32_t ah[4][4], al[4][4];                                                \
            _Pragma("unroll")                                                           \
            for (int mt = 0; mt < 4; mt++) {                                            \
                int ro = (mg * 64 + mt * 16 + g) * A_STRIDE + kbyte;                    \
                ah[mt][0] = LDS32(stb + SA_HI, ro);                                     \
                ah[mt][1] = LDS32(stb + SA_HI, ro + 8 * A_STRIDE);                      \
                ah[mt][2] = LDS32(stb + SA_HI, ro + 16);                                \
                ah[mt][3] = LDS32(stb + SA_HI, ro + 8 * A_STRIDE + 16);                 \
                al[mt][0] = LDS32(stb + SA_LO, ro);                                     \
                al[mt][1] = LDS32(stb + SA_LO, ro + 8 * A_STRIDE);                      \
                al[mt][2] = LDS32(stb + SA_LO, ro + 16);                                \
                al[mt][3] = LDS32(stb + SA_LO, ro + 8 * A_STRIDE + 16);                 \
            }                                                                           \
            _Pragma("unroll")                                                           \
            for (int jt = 0; jt < 2; jt++) {                                            \
                int nro0 = (jg * 16 + jt * 8 + g) * A_STRIDE + kbyte;                   \
                {   /* r-gate (B rows 0..63) */                                         \
                    uint32_t bh[2] = {LDS32(stb + SB, nro0),                            \
                                      LDS32(stb + SB, nro0 + 16)};                      \
                    _Pragma("unroll")                                                   \
                    for (int mt = 0; mt < 4; mt++) {                                    \
                        mma_fp16(accR[mt][jt], ah[mt], bh);                             \
                        mma_fp16(accR[mt][jt], al[mt], bh);                             \
                    }                                                                   \
                }                                                                       \
                {   /* z-gate (B rows 64..127) */                                       \
                    int nro = nro0 + 64 * A_STRIDE;                                     \
                    uint32_t bh[2] = {LDS32(stb + SB, nro),                             \
                                      LDS32(stb + SB, nro + 16)};                       \
                    _Pragma("unroll")                                                   \
                    for (int mt = 0; mt < 4; mt++) {                                    \
                        mma_fp16(accZ[mt][jt], ah[mt], bh);                             \
                        mma_fp16(accZ[mt][jt], al[mt], bh);                             \
                    }                                                                   \
                }                                                                       \
                {   /* n-gate (B rows 128..191) */                                      \
                    int nro = nro0 + 128 * A_STRIDE;                                    \
                    uint32_t bh[2] = {LDS32(stb + SB, nro),                             \
                                      LDS32(stb + SB, nro + 16)};                       \
                    _Pragma("unroll")                                                   \
                    for (int mt = 0; mt < 4; mt++) {                                    \
                        mma_fp16(ACCN[mt][jt], ah[mt], bh);                             \
                        mma_fp16(ACCN[mt][jt], al[mt], bh);                             \
                    }                                                                   \
                }                                                                       \
            }                                                                           \
        }                                                                               \
    } while (0)

__global__ __launch_bounds__(256, 1)
void gru_mma_kernel(const float *__restrict__ h, const float *__restrict__ bih,
                    const float *__restrict__ bhh, float *__restrict__ out) {
    extern __shared__ char smem[];
    __shared__ int srows[128];
    int tid = threadIdx.x, wid = tid >> 5, lane = tid & 31;
    int mg = wid >> 2, jg = wid & 3;          // 2 M-groups x 4 J-groups
    int g = lane >> 2, t = lane & 3;
    int rowbase = blockIdx.y * 128;
    int jb = blockIdx.x * 64;

    int n_keep = g_count;
    if (rowbase >= n_keep) return;

    if (tid < 128) {
        int slot = rowbase + tid;
        srows[tid] = (slot < n_keep) ? g_crow[slot] : 0;
    }
    __syncthreads();

    float accR[4][2][4] = {}, accZ[4][2][4] = {};
    float accNI[4][2][4] = {}, accNH[4][2][4] = {};

    char *st0 = smem, *st1 = smem + STAGE;
    load_chunk(0, st0, srows, jb, tid);
    asm volatile("cp.async.commit_group;" ::: "memory");
    load_chunk(1, st1, srows, jb, tid);
    asm volatile("cp.async.commit_group;" ::: "memory");

    for (int c = 0; c < NCHUNK; c++) {
        char *stb = (c & 1) ? st1 : st0;
        asm volatile("cp.async.wait_group 1;" ::: "memory");
        __syncthreads();
        if (c < 16) COMPUTE_CHUNK(stb, accNI);
        else        COMPUTE_CHUNK(stb, accNH);
        __syncthreads();
        if (c + 2 < NCHUNK) {
            load_chunk(c + 2, stb, srows, jb, tid);
            asm volatile("cp.async.commit_group;" ::: "memory");
        }
    }

    // ---- epilogue: GRU pointwise + scatter (all thread-local; rows distinct)
#pragma unroll
    for (int mt = 0; mt < 4; mt++) {
#pragma unroll
        for (int h2 = 0; h2 < 2; h2++) {
            int slot = rowbase + mg * 64 + mt * 16 + g + h2 * 8;
            if (slot < n_keep) {
                int hrow = g_cidx[slot];
#pragma unroll
                for (int jt = 0; jt < 2; jt++) {
#pragma unroll
                    for (int ec = 0; ec < 2; ec++) {
                        int e = h2 * 2 + ec;
                        int j = jb + jg * 16 + jt * 8 + t * 2 + ec;
                        float sr = accR[mt][jt][e] + bih[j] + bhh[j];
                        float sz = accZ[mt][jt][e] + bih[HID + j] + bhh[HID + j];
                        float si = accNI[mt][jt][e] + bih[2 * HID + j];
                        float sh = accNH[mt][jt][e] + bhh[2 * HID + j];
                        float r = 1.0f / (1.0f + expf(-sr));
                        float z = 1.0f / (1.0f + expf(-sz));
                        float n = tanhf(si + r * sh);
                        float hp = h[(size_t)hrow * HID + j];
                        out[(size_t)hrow * HID + j] = (1.0f - z) * n + z * hp;
                    }
                }
            }
        }
    }
}

// ---------- final loss reduction ----------
__global__ void loss_final_kernel(float *__restrict__ out, int nPart, long pos) {
    __shared__ float red[256];
    float s = 0.0f;
    for (int k = threadIdx.x; k < nPart; k += 256) s += g_lossPartial[k];
    red[threadIdx.x] = s;
    __syncthreads();
    for (int t = 128; t > 0; t >>= 1) {
        if (threadIdx.x < t) red[threadIdx.x] += red[threadIdx.x + t];
        __syncthreads();
    }
    if (threadIdx.x == 0) out[pos] = red[0];
}

// ---------- launch ----------
extern "C" void kernel_launch(void *const *d_in, const int *in_sizes, int n_in,
                              void *d_out, int out_size) {
    const float *h     = (const float *)d_in[0];
    const float *p     = (const float *)d_in[1];
    const float *X     = (const float *)d_in[2];
    const float *M     = (const float *)d_in[3];
    const int   *iobs  = (const int *)d_in[4];
    const float *wprep = (const float *)d_in[5];
    const float *bprep = (const float *)d_in[6];
    const float *wih   = (const float *)d_in[7];
    const float *whh   = (const float *)d_in[8];
    const float *bih   = (const float *)d_in[9];
    const float *bhh   = (const float *)d_in[10];

    int Nh = in_sizes[0] / HID;    // 100000
    int nobs = in_sizes[4];        // 50000
    float *out = (float *)d_out;

    cudaFuncSetAttribute(gru_mma_kernel, cudaFuncAttributeMaxDynamicSharedMemorySize,
                         GEMM_SMEM);

    long n4 = (long)Nh * HID / 4;
    copy_kernel<<<2048, 256>>>((float4 *)out, (const float4 *)h, n4);

    reset_kernel<<<1, 1>>>();
    compact_kernel<<<(nobs + 255) / 256, 256>>>(iobs, nobs);

    int nPrep = (nobs + 3) / 4;
    prep_kernel<<<nPrep, 256>>>(p, X, M, iobs, wprep, bprep, nobs);
    hconv_kernel<<<(int)(((long)nobs * 128 + 255) / 256), 256>>>(h, nobs);
    wconv_kernel<<<(KTOT * 384 + 255) / 256, 256>>>(wih, whh);

    dim3 grid(HID / 64, (nobs + 127) / 128);   // 8 x 391 static; blocks past
    gru_mma_kernel<<<grid, 256, GEMM_SMEM>>>(h, bih, bhh, out);  // g_count exit

    if ((long)out_size > (long)Nh * HID)
        loss_final_kernel<<<1, 256>>>(out, nPrep, (long)out_size - 1);
}

// round 13
// speedup vs baseline: 4.1445x; 1.3623x over previous
#include <cuda_runtime.h>
#include <cuda_fp16.h>
#include <math.h>
#include <stdint.h>

// GRUObservationCell on GB300 — mma.sync fp16 GEMM, ldmatrix fragments,
// 4-stage cp.async pipeline, row dedup. (harness PTX target is sm_103: no
// tcgen05; mma.sync.m16n8k16 + ldmatrix are baseline PTX and run on the
// tensor pipes.)
//   h[N=100000,512], p[N,128], X_obs[50000,64], M_obs[50000,64],
//   i_obs[50000] sorted int32, w_prep[64,4,16], bias_prep[64,16],
//   weight_ih[1536,1024], weight_hh[1536,512], bias_ih[1536], bias_hh[1536]
// out = h_new[N,512] ++ loss scalar.
//
// Math: gates = [x|h] @ [Wih|Whh]^T over unified K=1536, A and B in fp16
// (independent rounding errors ~1.4e-4 rel each -> ~2e-4 worst, measured
// slack 2.7x -> expect ~1.2e-4, gate is 1e-3). Duplicate i_obs rows (last
// occurrence wins) compacted out of the GEMM.

#define HID 512
#define DD 64
#define PH 16
#define KTOT 1536
#define NCHUNK 24
#define KCH 64
#define MAXROWS 50176

// ---------- static device scratch ----------
__device__ __half g_Ah[(size_t)MAXROWS * KTOT];
__device__ __half g_Bh[(size_t)KTOT * KTOT];
__device__ int   g_crow[MAXROWS];
__device__ int   g_cidx[MAXROWS];
__device__ int   g_count;
__device__ float g_lossPartial[MAXROWS / 4];

// ---------- helpers ----------
__device__ __forceinline__ uint32_t smem_u32(const void *p) {
    uint32_t a;
    asm("{ .reg .u64 t; cvta.to.shared.u64 t, %1; cvt.u32.u64 %0, t; }" : "=r"(a) : "l"(p));
    return a;
}
__device__ __forceinline__ void cpasync16(uint32_t dst, const void *src) {
    asm volatile("cp.async.cg.shared.global [%0], [%1], 16;" :: "r"(dst), "l"(src));
}
__device__ __forceinline__ void ldsm_x4(uint32_t (&r)[4], uint32_t addr) {
    asm volatile("ldmatrix.sync.aligned.m8n8.x4.shared.b16 {%0,%1,%2,%3}, [%4];"
                 : "=r"(r[0]), "=r"(r[1]), "=r"(r[2]), "=r"(r[3]) : "r"(addr));
}
__device__ __forceinline__ void mma_fp16(float (&d)[4], const uint32_t (&a)[4],
                                         uint32_t b0, uint32_t b1) {
    asm volatile(
        "mma.sync.aligned.m16n8k16.row.col.f32.f16.f16.f32 "
        "{%0,%1,%2,%3}, {%4,%5,%6,%7}, {%8,%9}, {%0,%1,%2,%3};"
        : "+f"(d[0]), "+f"(d[1]), "+f"(d[2]), "+f"(d[3])
        : "r"(a[0]), "r"(a[1]), "r"(a[2]), "r"(a[3]), "r"(b0), "r"(b1));
}

// ---------- h_new = h (bulk copy) ----------
__global__ void copy_kernel(float4 *__restrict__ dst, const float4 *__restrict__ src, long n4) {
    long i = (long)blockIdx.x * blockDim.x + threadIdx.x;
    long st = (long)gridDim.x * blockDim.x;
    for (; i < n4; i += st) dst[i] = src[i];
}

// ---------- compaction: last occurrence of each sorted i_obs value ----------
__global__ void reset_kernel() {
    if (threadIdx.x == 0) g_count = 0;
}
__global__ void compact_kernel(const int *__restrict__ iobs, int nobs) {
    int r = blockIdx.x * blockDim.x + threadIdx.x;
    if (r >= nobs) return;
    int v = iobs[r];
    bool keep = (r == nobs - 1) || (iobs[r + 1] != v);   // last occurrence wins
    if (keep) {
        int s = atomicAdd(&g_count, 1);   // unordered slots; each self-contained
        g_crow[s] = r;
        g_cidx[s] = v;
    }
}

// ---------- prep: features -> fp16 A-plane (k 0..1023, kept rows), loss ----------
// 256 thr = 4 rows x 64 d. Weights packed float4 per (ph,d): 1 LDS.128 per term.
__global__ void prep_kernel(const float *__restrict__ p, const float *__restrict__ X,
                            const float *__restrict__ Mm, const int *__restrict__ iobs,
                            const float *__restrict__ wprep, const float *__restrict__ bprep,
                            int nobs) {
    __shared__ float swf[64 * 16 * 4];   // [(ph*64+d)*4 + f]
    __shared__ float sbt[16 * 64];       // [ph*64 + d]
    __shared__ float red[256];
    int tid = threadIdx.x;
    for (int k = tid; k < 4096; k += 256) {
        int d = k >> 6, rem = k & 63, f = rem >> 4, ph = rem & 15;
        swf[(ph * 64 + d) * 4 + f] = wprep[k];
    }
    for (int k = tid; k < 1024; k += 256) sbt[(k & 15) * 64 + (k >> 4)] = bprep[k];
    __syncthreads();

    int d = tid & 63;
    int row = blockIdx.x * 4 + (tid >> 6);
    float lossd = 0.0f;
    if (row < nobs) {
        int iidx = iobs[row];
        float mean = p[(size_t)iidx * 128 + d];
        float var  = fabsf(p[(size_t)iidx * 128 + 64 + d]) + 1e-6f;
        float xv   = X[(size_t)row * DD + d];
        float m    = Mm[(size_t)row * DD + d];
        float err  = (xv - mean) * rsqrtf(var);
        lossd = 0.5f * (err * err + logf(var)) * m;

        bool kept = (row == nobs - 1) || (iobs[row + 1] != iidx);
        if (kept) {
            __half oh[16];
#pragma unroll
            for (int ph = 0; ph < PH; ph++) {
                float4 wv = *reinterpret_cast<const float4 *>(&swf[(ph * 64 + d) * 4]);
                float v = xv * wv.x + mean * wv.y + var * wv.z + err * wv.w +
                          sbt[ph * 64 + d];
                oh[ph] = __float2half_rn(fmaxf(v, 0.0f) * m);
            }
            uint4 *ph4 = reinterpret_cast<uint4 *>(oh);
            uint4 *dh = reinterpret_cast<uint4 *>(&g_Ah[(size_t)row * KTOT + d * PH]);
            dh[0] = ph4[0]; dh[1] = ph4[1];
        }
    }
    red[tid] = lossd;
    __syncthreads();
    for (int s = 128; s > 0; s >>= 1) {
        if (tid < s) red[tid] += red[tid + s];
        __syncthreads();
    }
    if (tid == 0) g_lossPartial[blockIdx.x] = red[0];
}

// ---------- gather h rows (kept only) -> A-plane cols 1024..1535 ----------
__global__ void hconv_kernel(const float *__restrict__ h, int nobs) {
    long idx = (long)blockIdx.x * 256 + threadIdx.x;  // slot*128 + q
    int slot = (int)(idx >> 7);
    if (slot >= g_count) return;
    int q = (int)(idx & 127);
    int r = g_crow[slot];
    int hrow = g_cidx[slot];
    float4 v = *reinterpret_cast<const float4 *>(&h[(size_t)hrow * HID + q * 4]);
    __half oh[4];
    oh[0] = __float2half_rn(v.x); oh[1] = __float2half_rn(v.y);
    oh[2] = __float2half_rn(v.z); oh[3] = __float2half_rn(v.w);
    *reinterpret_cast<uint2 *>(&g_Ah[(size_t)r * KTOT + 1024 + q * 4]) =
        *reinterpret_cast<uint2 *>(oh);
}

// ---------- weights -> fp16 B-plane [1536 gates][1536 k] ----------
__global__ void wconv_kernel(const float *__restrict__ wih, const float *__restrict__ whh) {
    int idx = blockIdx.x * 256 + threadIdx.x;  // over 1536*384 float4 units
    if (idx >= KTOT * 384) return;
    int g = idx / 384, q = idx - g * 384;
    int k = q * 4;
    float4 v = (k < 1024)
                   ? *reinterpret_cast<const float4 *>(&wih[(size_t)g * 1024 + k])
                   : *reinterpret_cast<const float4 *>(&whh[(size_t)g * 512 + (k - 1024)]);
    __half o[4];
    o[0] = __float2half_rn(v.x); o[1] = __float2half_rn(v.y);
    o[2] = __float2half_rn(v.z); o[3] = __float2half_rn(v.w);
    *reinterpret_cast<uint2 *>(&g_Bh[(size_t)g * KTOT + k]) = *reinterpret_cast<uint2 *>(o);
}

// ---------- main MMA GEMM + GRU epilogue ----------
// stage (row stride 144B, conflict-free for ldmatrix: banks step 4/row):
//   A 128x144 = 18432 | B 192x144 = 27648   -> 46080/stage, 4 stages
#define A_STRIDE 144
#define SA 0
#define SB 18432
#define STAGE 46080
#define NSTAGE 4
#define GEMM_SMEM (NSTAGE * STAGE)   // 184320

__device__ __forceinline__ void load_chunk(int c, char *stb, const int *srows, int jb,
                                           int tid) {
    size_t kof = (size_t)c * KCH;
#pragma unroll
    for (int u = 0; u < 4; u++) {            // A: 128 rows x 8 granules of 16B
        int idx = tid + u * 256;
        int r = idx >> 3, gq = idx & 7;
        cpasync16(smem_u32(stb + SA + r * A_STRIDE + gq * 16),
                  g_Ah + (size_t)srows[r] * KTOT + kof + gq * 8);
    }
#pragma unroll
    for (int u = 0; u < 6; u++) {            // B: 192 rows x 8 granules
        int idx = tid + u * 256;
        int r = idx >> 3, gq = idx & 7;
        int grow = (r >> 6) * HID + jb + (r & 63);   // gate*512 + jb + jr
        cpasync16(smem_u32(stb + SB + r * A_STRIDE + gq * 16),
                  g_Bh + (size_t)grow * KTOT + kof + gq * 8);
    }
}

__global__ __launch_bounds__(256, 1)
void gru_mma_kernel(const float *__restrict__ h, const float *__restrict__ bih,
                    const float *__restrict__ bhh, float *__restrict__ out) {
    extern __shared__ char smem[];
    __shared__ int srows[128];
    int tid = threadIdx.x, wid = tid >> 5, lane = tid & 31;
    int mg = wid >> 2, jg = wid & 3;          // 2 M-groups x 4 J-groups
    int g = lane >> 2, t = lane & 3;
    int rowbase = blockIdx.y * 128;
    int jb = blockIdx.x * 64;

    int n_keep = g_count;
    if (rowbase >= n_keep) return;

    if (tid < 128) {
        int slot = rowbase + tid;
        srows[tid] = (slot < n_keep) ? g_crow[slot] : 0;
    }
    __syncthreads();

    // ldmatrix per-lane address offsets (within a stage)
    // A x4 tile (16x16): rows = base + (lane&15), byte half = (lane>>4)*16
    uint32_t aoff = SA + (uint32_t)(mg * 64 + (lane & 15)) * A_STRIDE + ((lane >> 4) << 4);
    // B x4 tile (n16 x k16): rows jg*16 + (lane&7) + ((lane&16)>>1), byte half (lane&8)*2
    uint32_t boff = SB + (uint32_t)(jg * 16 + (lane & 7) + ((lane & 16) >> 1)) * A_STRIDE +
                    ((lane & 8) << 1);

    float accR[4][2][4] = {}, accZ[4][2][4] = {};
    float accNI[4][2][4] = {}, accNH[4][2][4] = {};

    load_chunk(0, smem, srows, jb, tid);
    asm volatile("cp.async.commit_group;" ::: "memory");
    load_chunk(1, smem + STAGE, srows, jb, tid);
    asm volatile("cp.async.commit_group;" ::: "memory");
    load_chunk(2, smem + 2 * STAGE, srows, jb, tid);
    asm volatile("cp.async.commit_group;" ::: "memory");

    for (int c = 0; c < NCHUNK; c++) {
        char *stb = smem + (size_t)(c & 3) * STAGE;
        asm volatile("cp.async.wait_group 2;" ::: "memory");
        __syncthreads();
        // prefetch chunk c+3 into buffer (c+3)&3 == (c-1)&3 (consumer done)
        if (c + 3 < NCHUNK) {
            load_chunk(c + 3, smem + (size_t)((c + 3) & 3) * STAGE, srows, jb, tid);
        }
        asm volatile("cp.async.commit_group;" ::: "memory");

        uint32_t sb32 = smem_u32(stb);
#pragma unroll
        for (int kk = 0; kk < 4; kk++) {
            uint32_t a[4][4];
#pragma unroll
            for (int mt = 0; mt < 4; mt++)
                ldsm_x4(a[mt], sb32 + aoff + mt * (16 * A_STRIDE) + kk * 32);
            uint32_t bR[4], bZ[4], bN[4];
            ldsm_x4(bR, sb32 + boff + kk * 32);
            ldsm_x4(bZ, sb32 + boff + 64 * A_STRIDE + kk * 32);
            ldsm_x4(bN, sb32 + boff + 128 * A_STRIDE + kk * 32);
#pragma unroll
            for (int mt = 0; mt < 4; mt++) {
                mma_fp16(accR[mt][0], a[mt], bR[0], bR[1]);
                mma_fp16(accR[mt][1], a[mt], bR[2], bR[3]);
                mma_fp16(accZ[mt][0], a[mt], bZ[0], bZ[1]);
                mma_fp16(accZ[mt][1], a[mt], bZ[2], bZ[3]);
                if (c < 16) {
                    mma_fp16(accNI[mt][0], a[mt], bN[0], bN[1]);
                    mma_fp16(accNI[mt][1], a[mt], bN[2], bN[3]);
                } else {
                    mma_fp16(accNH[mt][0], a[mt], bN[0], bN[1]);
                    mma_fp16(accNH[mt][1], a[mt], bN[2], bN[3]);
                }
            }
        }
    }

    // ---- epilogue: GRU pointwise + scatter (all thread-local; rows distinct)
#pragma unroll
    for (int mt = 0; mt < 4; mt++) {
#pragma unroll
        for (int h2 = 0; h2 < 2; h2++) {
            int slot = rowbase + mg * 64 + mt * 16 + g + h2 * 8;
            if (slot < n_keep) {
                int hrow = g_cidx[slot];
#pragma unroll
                for (int jt = 0; jt < 2; jt++) {
#pragma unroll
                    for (int ec = 0; ec < 2; ec++) {
                        int e = h2 * 2 + ec;
                        int j = jb + jg * 16 + jt * 8 + t * 2 + ec;
                        float sr = accR[mt][jt][e] + bih[j] + bhh[j];
                        float sz = accZ[mt][jt][e] + bih[HID + j] + bhh[HID + j];
                        float si = accNI[mt][jt][e] + bih[2 * HID + j];
                        float sh = accNH[mt][jt][e] + bhh[2 * HID + j];
                        float r = 1.0f / (1.0f + expf(-sr));
                        float z = 1.0f / (1.0f + expf(-sz));
                        float n = tanhf(si + r * sh);
                        float hp = h[(size_t)hrow * HID + j];
                        out[(size_t)hrow * HID + j] = (1.0f - z) * n + z * hp;
                    }
                }
            }
        }
    }
}

// ---------- final loss reduction ----------
__global__ void loss_final_kernel(float *__restrict__ out, int nPart, long pos) {
    __shared__ float red[256];
    float s = 0.0f;
    for (int k = threadIdx.x; k < nPart; k += 256) s += g_lossPartial[k];
    red[threadIdx.x] = s;
    __syncthreads();
    for (int t = 128; t > 0; t >>= 1) {
        if (threadIdx.x < t) red[threadIdx.x] += red[threadIdx.x + t];
        __syncthreads();
    }
    if (threadIdx.x == 0) out[pos] = red[0];
}

// ---------- launch ----------
extern "C" void kernel_launch(void *const *d_in, const int *in_sizes, int n_in,
                              void *d_out, int out_size) {
    const float *h     = (const float *)d_in[0];
    const float *p     = (const float *)d_in[1];
    const float *X     = (const float *)d_in[2];
    const float *M     = (const float *)d_in[3];
    const int   *iobs  = (const int *)d_in[4];
    const float *wprep = (const float *)d_in[5];
    const float *bprep = (const float *)d_in[6];
    const float *wih   = (const float *)d_in[7];
    const float *whh   = (const float *)d_in[8];
    const float *bih   = (const float *)d_in[9];
    const float *bhh   = (const float *)d_in[10];

    int Nh = in_sizes[0] / HID;    // 100000
    int nobs = in_sizes[4];        // 50000
    float *out = (float *)d_out;

    cudaFuncSetAttribute(gru_mma_kernel, cudaFuncAttributeMaxDynamicSharedMemorySize,
                         GEMM_SMEM);

    long n4 = (long)Nh * HID / 4;
    copy_kernel<<<2048, 256>>>((float4 *)out, (const float4 *)h, n4);

    reset_kernel<<<1, 1>>>();
    compact_kernel<<<(nobs + 255) / 256, 256>>>(iobs, nobs);

    int nPrep = (nobs + 3) / 4;
    prep_kernel<<<nPrep, 256>>>(p, X, M, iobs, wprep, bprep, nobs);
    hconv_kernel<<<(int)(((long)nobs * 128 + 255) / 256), 256>>>(h, nobs);
    wconv_kernel<<<(KTOT * 384 + 255) / 256, 256>>>(wih, whh);

    dim3 grid(HID / 64, (nobs + 127) / 128);   // 8 x 391 static; g_count exit
    gru_mma_kernel<<<grid, 256, GEMM_SMEM>>>(h, bih, bhh, out);

    if ((long)out_size > (long)Nh * HID)
        loss_final_kernel<<<1, 256>>>(out, nPrep, (long)out_size - 1);
}

// round 15
// speedup vs baseline: 4.8306x; 1.1655x over previous
#include <cuda_runtime.h>
#include <cuda_fp16.h>
#include <math.h>
#include <stdint.h>

// GRUObservationCell on GB300 — mma.sync fp16 GEMM, ldmatrix fragments,
// 4-stage cp.async pipeline, 16 warps/CTA (4/SMSP), row dedup.
// (harness PTX target is sm_103: no tcgen05; mma.sync.m16n8k16 + ldmatrix
// are baseline PTX and run on the tensor pipes.)
//   h[N=100000,512], p[N,128], X_obs[50000,64], M_obs[50000,64],
//   i_obs[50000] sorted int32, w_prep[64,4,16], bias_prep[64,16],
//   weight_ih[1536,1024], weight_hh[1536,512], bias_ih[1536], bias_hh[1536]
// out = h_new[N,512] ++ loss scalar.
//
// Math: gates = [x|h] @ [Wih|Whh]^T over unified K=1536, A and B in fp16
// (measured rel_err ~7e-5 vs 1e-3 gate). Duplicate i_obs rows (last
// occurrence wins) compacted out of the GEMM.

#define HID 512
#define DD 64
#define PH 16
#define KTOT 1536
#define NCHUNK 24
#define KCH 64
#define MAXROWS 50176

// ---------- static device scratch ----------
__device__ __half g_Ah[(size_t)MAXROWS * KTOT];
__device__ __half g_Bh[(size_t)KTOT * KTOT];
__device__ int   g_crow[MAXROWS];
__device__ int   g_cidx[MAXROWS];
__device__ int   g_count;
__device__ float g_lossPartial[MAXROWS / 16];

// ---------- helpers ----------
__device__ __forceinline__ uint32_t smem_u32(const void *p) {
    uint32_t a;
    asm("{ .reg .u64 t; cvta.to.shared.u64 t, %1; cvt.u32.u64 %0, t; }" : "=r"(a) : "l"(p));
    return a;
}
__device__ __forceinline__ void cpasync16(uint32_t dst, const void *src) {
    asm volatile("cp.async.cg.shared.global [%0], [%1], 16;" :: "r"(dst), "l"(src));
}
__device__ __forceinline__ void ldsm_x4(uint32_t (&r)[4], uint32_t addr) {
    asm volatile("ldmatrix.sync.aligned.m8n8.x4.shared.b16 {%0,%1,%2,%3}, [%4];"
                 : "=r"(r[0]), "=r"(r[1]), "=r"(r[2]), "=r"(r[3]) : "r"(addr));
}
__device__ __forceinline__ void mma_fp16(float (&d)[4], const uint32_t (&a)[4],
                                         uint32_t b0, uint32_t b1) {
    asm volatile(
        "mma.sync.aligned.m16n8k16.row.col.f32.f16.f16.f32 "
        "{%0,%1,%2,%3}, {%4,%5,%6,%7}, {%8,%9}, {%0,%1,%2,%3};"
        : "+f"(d[0]), "+f"(d[1]), "+f"(d[2]), "+f"(d[3])
        : "r"(a[0]), "r"(a[1]), "r"(a[2]), "r"(a[3]), "r"(b0), "r"(b1));
}

// ---------- h_new = h (bulk copy) ----------
__global__ void copy_kernel(float4 *__restrict__ dst, const float4 *__restrict__ src, long n4) {
    long i = (long)blockIdx.x * blockDim.x + threadIdx.x;
    long st = (long)gridDim.x * blockDim.x;
    for (; i < n4; i += st) dst[i] = src[i];
}

// ---------- compaction: last occurrence of each sorted i_obs value ----------
__global__ void reset_kernel() {
    if (threadIdx.x == 0) g_count = 0;
}
__global__ void compact_kernel(const int *__restrict__ iobs, int nobs) {
    int r = blockIdx.x * blockDim.x + threadIdx.x;
    if (r >= nobs) return;
    int v = iobs[r];
    bool keep = (r == nobs - 1) || (iobs[r + 1] != v);   // last occurrence wins
    if (keep) {
        int s = atomicAdd(&g_count, 1);   // unordered slots; each self-contained
        g_crow[s] = r;
        g_cidx[s] = v;
    }
}

// ---------- prep: features -> fp16 A-plane (k 0..1023, kept rows), loss ----------
// 256 thr = 64 d-lanes x 4 row-groups; each thread processes 4 rows for its d,
// so each weight float4 is loaded once per ph and reused across 4 rows.
__global__ void prep_kernel(const float *__restrict__ p, const float *__restrict__ X,
                            const float *__restrict__ Mm, const int *__restrict__ iobs,
                            const float *__restrict__ wprep, const float *__restrict__ bprep,
                            int nobs) {
    __shared__ float swf[64 * 16 * 4];   // [(ph*64+d)*4 + f]
    __shared__ float sbt[16 * 64];       // [ph*64 + d]
    __shared__ float red[256];
    int tid = threadIdx.x;
    for (int k = tid; k < 4096; k += 256) {
        int d = k >> 6, rem = k & 63, f = rem >> 4, ph = rem & 15;
        swf[(ph * 64 + d) * 4 + f] = wprep[k];
    }
    for (int k = tid; k < 1024; k += 256) sbt[(k & 15) * 64 + (k >> 4)] = bprep[k];
    __syncthreads();

    int d = tid & 63;
    int rbase = blockIdx.x * 16 + (tid >> 6) * 4;

    float xv[4], mean[4], var[4], err[4], msk[4];
    int rowi[4];
    bool valid[4], kept[4];
    float lossd = 0.0f;
#pragma unroll
    for (int i = 0; i < 4; i++) {
        int row = rbase + i;
        rowi[i] = row;
        valid[i] = row < nobs;
        kept[i] = false;
        if (valid[i]) {
            int iidx = iobs[row];
            mean[i] = p[(size_t)iidx * 128 + d];
            var[i]  = fabsf(p[(size_t)iidx * 128 + 64 + d]) + 1e-6f;
            xv[i]   = X[(size_t)row * DD + d];
            msk[i]  = Mm[(size_t)row * DD + d];
            err[i]  = (xv[i] - mean[i]) * rsqrtf(var[i]);
            lossd += 0.5f * (err[i] * err[i] + logf(var[i])) * msk[i];
            kept[i] = (row == nobs - 1) || (iobs[row + 1] != iidx);
        }
    }

    __half oh[4][16];
#pragma unroll
    for (int ph = 0; ph < PH; ph++) {
        float4 wv = *reinterpret_cast<const float4 *>(&swf[(ph * 64 + d) * 4]);
        float b = sbt[ph * 64 + d];
#pragma unroll
        for (int i = 0; i < 4; i++) {
            float v = xv[i] * wv.x + mean[i] * wv.y + var[i] * wv.z + err[i] * wv.w + b;
            oh[i][ph] = __float2half_rn(fmaxf(v, 0.0f) * msk[i]);
        }
    }
#pragma unroll
    for (int i = 0; i < 4; i++) {
        if (kept[i]) {
            uint4 *src = reinterpret_cast<uint4 *>(oh[i]);
            uint4 *dst = reinterpret_cast<uint4 *>(&g_Ah[(size_t)rowi[i] * KTOT + d * PH]);
            dst[0] = src[0]; dst[1] = src[1];
        }
    }

    red[tid] = lossd;
    __syncthreads();
    for (int s = 128; s > 0; s >>= 1) {
        if (tid < s) red[tid] += red[tid + s];
        __syncthreads();
    }
    if (tid == 0) g_lossPartial[blockIdx.x] = red[0];
}

// ---------- gather h rows (kept only) -> A-plane cols 1024..1535 ----------
__global__ void hconv_kernel(const float *__restrict__ h, int nobs) {
    long idx = (long)blockIdx.x * 256 + threadIdx.x;  // slot*128 + q
    int slot = (int)(idx >> 7);
    if (slot >= g_count) return;
    int q = (int)(idx & 127);
    int r = g_crow[slot];
    int hrow = g_cidx[slot];
    float4 v = *reinterpret_cast<const float4 *>(&h[(size_t)hrow * HID + q * 4]);
    __half oh[4];
    oh[0] = __float2half_rn(v.x); oh[1] = __float2half_rn(v.y);
    oh[2] = __float2half_rn(v.z); oh[3] = __float2half_rn(v.w);
    *reinterpret_cast<uint2 *>(&g_Ah[(size_t)r * KTOT + 1024 + q * 4]) =
        *reinterpret_cast<uint2 *>(oh);
}

// ---------- weights -> fp16 B-plane [1536 gates][1536 k] ----------
__global__ void wconv_kernel(const float *__restrict__ wih, const float *__restrict__ whh) {
    int idx = blockIdx.x * 256 + threadIdx.x;  // over 1536*384 float4 units
    if (idx >= KTOT * 384) return;
    int g = idx / 384, q = idx - g * 384;
    int k = q * 4;
    float4 v = (k < 1024)
                   ? *reinterpret_cast<const float4 *>(&wih[(size_t)g * 1024 + k])
                   : *reinterpret_cast<const float4 *>(&whh[(size_t)g * 512 + (k - 1024)]);
    __half o[4];
    o[0] = __float2half_rn(v.x); o[1] = __float2half_rn(v.y);
    o[2] = __float2half_rn(v.z); o[3] = __float2half_rn(v.w);
    *reinterpret_cast<uint2 *>(&g_Bh[(size_t)g * KTOT + k]) = *reinterpret_cast<uint2 *>(o);
}

// ---------- main MMA GEMM + GRU epilogue ----------
// stage (row stride 144B, conflict-free for ldmatrix: banks step 4/row):
//   A 128x144 = 18432 | B 192x144 = 27648   -> 46080/stage, 4 stages
#define A_STRIDE 144
#define SA 0
#define SB 18432
#define STAGE 46080
#define NSTAGE 4
#define GEMM_SMEM (NSTAGE * STAGE)   // 184320
#define NT 512                       // 16 warps = 4 per SMSP

__device__ __forceinline__ void load_chunk(int c, char *stb, const int *srows, int jb,
                                           int tid) {
    size_t kof = (size_t)c * KCH;
#pragma unroll
    for (int u = 0; u < 2; u++) {            // A: 128 rows x 8 granules of 16B
        int idx = tid + u * NT;
        int r = idx >> 3, gq = idx & 7;
        cpasync16(smem_u32(stb + SA + r * A_STRIDE + gq * 16),
                  g_Ah + (size_t)srows[r] * KTOT + kof + gq * 8);
    }
#pragma unroll
    for (int u = 0; u < 3; u++) {            // B: 192 rows x 8 granules
        int idx = tid + u * NT;
        int r = idx >> 3, gq = idx & 7;
        int grow = (r >> 6) * HID + jb + (r & 63);   // gate*512 + jb + jr
        cpasync16(smem_u32(stb + SB + r * A_STRIDE + gq * 16),
                  g_Bh + (size_t)grow * KTOT + kof + gq * 8);
    }
}

__global__ __launch_bounds__(NT, 1)
void gru_mma_kernel(const float *__restrict__ h, const float *__restrict__ bih,
                    const float *__restrict__ bhh, float *__restrict__ out) {
    extern __shared__ char smem[];
    __shared__ int srows[128];
    int tid = threadIdx.x, wid = tid >> 5, lane = tid & 31;
    int mg = wid >> 2, jg = wid & 3;          // 4 M-groups (32 rows) x 4 J-groups
    int g = lane >> 2, t = lane & 3;
    int rowbase = blockIdx.y * 128;
    int jb = blockIdx.x * 64;

    int n_keep = g_count;
    if (rowbase >= n_keep) return;

    if (tid < 128) {
        int slot = rowbase + tid;
        srows[tid] = (slot < n_keep) ? g_crow[slot] : 0;
    }
    __syncthreads();

    // ldmatrix per-lane address offsets (within a stage)
    uint32_t aoff = SA + (uint32_t)(mg * 32 + (lane & 15)) * A_STRIDE + ((lane >> 4) << 4);
    uint32_t boff = SB + (uint32_t)(jg * 16 + (lane & 7) + ((lane & 16) >> 1)) * A_STRIDE +
                    ((lane & 8) << 1);

    float accR[2][2][4] = {}, accZ[2][2][4] = {};
    float accNI[2][2][4] = {}, accNH[2][2][4] = {};

    load_chunk(0, smem, srows, jb, tid);
    asm volatile("cp.async.commit_group;" ::: "memory");
    load_chunk(1, smem + STAGE, srows, jb, tid);
    asm volatile("cp.async.commit_group;" ::: "memory");
    load_chunk(2, smem + 2 * STAGE, srows, jb, tid);
    asm volatile("cp.async.commit_group;" ::: "memory");

    for (int c = 0; c < NCHUNK; c++) {
        char *stb = smem + (size_t)(c & 3) * STAGE;
        asm volatile("cp.async.wait_group 2;" ::: "memory");
        __syncthreads();
        // prefetch chunk c+3 into buffer (c+3)&3 == (c-1)&3 (consumer done)
        if (c + 3 < NCHUNK) {
            load_chunk(c + 3, smem + (size_t)((c + 3) & 3) * STAGE, srows, jb, tid);
        }
        asm volatile("cp.async.commit_group;" ::: "memory");

        uint32_t sb32 = smem_u32(stb);
#pragma unroll
        for (int kk = 0; kk < 4; kk++) {
            uint32_t a[2][4];
            ldsm_x4(a[0], sb32 + aoff + kk * 32);
            ldsm_x4(a[1], sb32 + aoff + 16 * A_STRIDE + kk * 32);
            uint32_t bR[4], bZ[4], bN[4];
            ldsm_x4(bR, sb32 + boff + kk * 32);
            ldsm_x4(bZ, sb32 + boff + 64 * A_STRIDE + kk * 32);
            ldsm_x4(bN, sb32 + boff + 128 * A_STRIDE + kk * 32);
#pragma unroll
            for (int mt = 0; mt < 2; mt++) {
                mma_fp16(accR[mt][0], a[mt], bR[0], bR[1]);
                mma_fp16(accR[mt][1], a[mt], bR[2], bR[3]);
                mma_fp16(accZ[mt][0], a[mt], bZ[0], bZ[1]);
                mma_fp16(accZ[mt][1], a[mt], bZ[2], bZ[3]);
                if (c < 16) {
                    mma_fp16(accNI[mt][0], a[mt], bN[0], bN[1]);
                    mma_fp16(accNI[mt][1], a[mt], bN[2], bN[3]);
                } else {
                    mma_fp16(accNH[mt][0], a[mt], bN[0], bN[1]);
                    mma_fp16(accNH[mt][1], a[mt], bN[2], bN[3]);
                }
            }
        }
    }

    // ---- epilogue: GRU pointwise + scatter (all thread-local; rows distinct)
#pragma unroll
    for (int mt = 0; mt < 2; mt++) {
#pragma unroll
        for (int h2 = 0; h2 < 2; h2++) {
            int slot = rowbase + mg * 32 + mt * 16 + g + h2 * 8;
            if (slot < n_keep) {
                int hrow = g_cidx[slot];
#pragma unroll
                for (int jt = 0; jt < 2; jt++) {
#pragma unroll
                    for (int ec = 0; ec < 2; ec++) {
                        int e = h2 * 2 + ec;
                        int j = jb + jg * 16 + jt * 8 + t * 2 + ec;
                        float sr = accR[mt][jt][e] + bih[j] + bhh[j];
                        float sz = accZ[mt][jt][e] + bih[HID + j] + bhh[HID + j];
                        float si = accNI[mt][jt][e] + bih[2 * HID + j];
                        float sh = accNH[mt][jt][e] + bhh[2 * HID + j];
                        float r = 1.0f / (1.0f + expf(-sr));
                        float z = 1.0f / (1.0f + expf(-sz));
                        float n = tanhf(si + r * sh);
                        float hp = h[(size_t)hrow * HID + j];
                        out[(size_t)hrow * HID + j] = (1.0f - z) * n + z * hp;
                    }
                }
            }
        }
    }
}

// ---------- final loss reduction ----------
__global__ void loss_final_kernel(float *__restrict__ out, int nPart, long pos) {
    __shared__ float red[256];
    float s = 0.0f;
    for (int k = threadIdx.x; k < nPart; k += 256) s += g_lossPartial[k];
    red[threadIdx.x] = s;
    __syncthreads();
    for (int t = 128; t > 0; t >>= 1) {
        if (threadIdx.x < t) red[threadIdx.x] += red[threadIdx.x + t];
        __syncthreads();
    }
    if (threadIdx.x == 0) out[pos] = red[0];
}

// ---------- launch ----------
extern "C" void kernel_launch(void *const *d_in, const int *in_sizes, int n_in,
                              void *d_out, int out_size) {
    const float *h     = (const float *)d_in[0];
    const float *p     = (const float *)d_in[1];
    const float *X     = (const float *)d_in[2];
    const float *M     = (const float *)d_in[3];
    const int   *iobs  = (const int *)d_in[4];
    const float *wprep = (const float *)d_in[5];
    const float *bprep = (const float *)d_in[6];
    const float *wih   = (const float *)d_in[7];
    const float *whh   = (const float *)d_in[8];
    const float *bih   = (const float *)d_in[9];
    const float *bhh   = (const float *)d_in[10];

    int Nh = in_sizes[0] / HID;    // 100000
    int nobs = in_sizes[4];        // 50000
    float *out = (float *)d_out;

    cudaFuncSetAttribute(gru_mma_kernel, cudaFuncAttributeMaxDynamicSharedMemorySize,
                         GEMM_SMEM);

    long n4 = (long)Nh * HID / 4;
    copy_kernel<<<4096, 256>>>((float4 *)out, (const float4 *)h, n4);

    reset_kernel<<<1, 1>>>();
    compact_kernel<<<(nobs + 255) / 256, 256>>>(iobs, nobs);

    int nPrep = (nobs + 15) / 16;
    prep_kernel<<<nPrep, 256>>>(p, X, M, iobs, wprep, bprep, nobs);
    hconv_kernel<<<(int)(((long)nobs * 128 + 255) / 256), 256>>>(h, nobs);
    wconv_kernel<<<(KTOT * 384 + 255) / 256, 256>>>(wih, whh);

    dim3 grid(HID / 64, (nobs + 127) / 128);   // 8 x 391 static; g_count exit
    gru_mma_kernel<<<grid, NT, GEMM_SMEM>>>(h, bih, bhh, out);

    if ((long)out_size > (long)Nh * HID)
        loss_final_kernel<<<1, 256>>>(out, nPrep, (long)out_size - 1);
}

// round 17
// speedup vs baseline: 5.5214x; 1.1430x over previous
#include <cuda_runtime.h>
#include <cuda_fp16.h>
#include <math.h>
#include <stdint.h>

// GRUObservationCell on GB300 — mma.sync fp16 GEMM, ldmatrix fragments,
// 5-stage cp.async pipeline, 16 warps/CTA, row dedup, skip-copy bitmap.
// (harness PTX target is sm_103: no tcgen05; mma.sync.m16n8k16 + ldmatrix
// are baseline PTX and run on the tensor pipes at ~288 TF/s fp16.)
//   h[N=100000,512], p[N,128], X_obs[50000,64], M_obs[50000,64],
//   i_obs[50000] sorted int32, w_prep[64,4,16], bias_prep[64,16],
//   weight_ih[1536,1024], weight_hh[1536,512], bias_ih[1536], bias_hh[1536]
// out = h_new[N,512] ++ loss scalar.
//
// Math: gates = [x|h] @ [Wih|Whh]^T over unified K=1536, A and B in fp16
// (measured rel_err ~7e-5 vs 1e-3 gate). Duplicate i_obs rows (last
// occurrence wins) compacted out of the GEMM; kept-row bitmap lets the
// bulk h->out copy skip rows the GEMM rewrites.

#define HID 512
#define DD 64
#define PH 16
#define KTOT 1536
#define NCHUNK 24
#define KCH 64
#define MAXROWS 50176

// ---------- static device scratch ----------
__device__ __half g_Ah[(size_t)MAXROWS * KTOT];
__device__ __half g_Bh[(size_t)KTOT * KTOT];
__device__ int      g_crow[MAXROWS];
__device__ int      g_cidx[MAXROWS];
__device__ int      g_count;
__device__ uint32_t g_skip[4096];          // bitmap over h rows (kept -> skip copy)
__device__ float    g_lossPartial[MAXROWS / 8];

// ---------- helpers ----------
__device__ __forceinline__ uint32_t smem_u32(const void *p) {
    uint32_t a;
    asm("{ .reg .u64 t; cvta.to.shared.u64 t, %1; cvt.u32.u64 %0, t; }" : "=r"(a) : "l"(p));
    return a;
}
__device__ __forceinline__ void cpasync16(uint32_t dst, const void *src) {
    asm volatile("cp.async.cg.shared.global [%0], [%1], 16;" :: "r"(dst), "l"(src));
}
__device__ __forceinline__ void ldsm_x4(uint32_t (&r)[4], uint32_t addr) {
    asm volatile("ldmatrix.sync.aligned.m8n8.x4.shared.b16 {%0,%1,%2,%3}, [%4];"
                 : "=r"(r[0]), "=r"(r[1]), "=r"(r[2]), "=r"(r[3]) : "r"(addr));
}
__device__ __forceinline__ void mma_fp16(float (&d)[4], const uint32_t (&a)[4],
                                         uint32_t b0, uint32_t b1) {
    asm volatile(
        "mma.sync.aligned.m16n8k16.row.col.f32.f16.f16.f32 "
        "{%0,%1,%2,%3}, {%4,%5,%6,%7}, {%8,%9}, {%0,%1,%2,%3};"
        : "+f"(d[0]), "+f"(d[1]), "+f"(d[2]), "+f"(d[3])
        : "r"(a[0]), "r"(a[1]), "r"(a[2]), "r"(a[3]), "r"(b0), "r"(b1));
}

// ---------- reset: counter + skip bitmap ----------
__global__ void reset_kernel() {
    int i = blockIdx.x * blockDim.x + threadIdx.x;
    if (i < 4096) g_skip[i] = 0;
    if (i == 0) g_count = 0;
}

// ---------- compaction: last occurrence of each sorted i_obs value ----------
__global__ void compact_kernel(const int *__restrict__ iobs, int nobs) {
    int r = blockIdx.x * blockDim.x + threadIdx.x;
    if (r >= nobs) return;
    int v = iobs[r];
    bool keep = (r == nobs - 1) || (iobs[r + 1] != v);   // last occurrence wins
    if (keep) {
        int s = atomicAdd(&g_count, 1);   // unordered slots; each self-contained
        g_crow[s] = r;
        g_cidx[s] = v;
        atomicOr(&g_skip[v >> 5], 1u << (v & 31));
    }
}

// ---------- h_new = h for rows the GEMM won't rewrite ----------
__global__ void copy_kernel(float4 *__restrict__ dst, const float4 *__restrict__ src, long n4) {
    long i = (long)blockIdx.x * blockDim.x + threadIdx.x;
    long st = (long)gridDim.x * blockDim.x;
    for (; i < n4; i += st) {
        int row = (int)(i >> 7);          // 128 float4 per row
        if (!((g_skip[row >> 5] >> (row & 31)) & 1u)) dst[i] = src[i];
    }
}

// ---------- prep: features -> fp16 A-plane (k 0..1023, kept rows), loss ----------
// 256 thr = 64 d-lanes x 4 groups of 2 rows (8 rows/block): weight float4
// loaded once per ph, reused across 2 rows; low reg pressure -> high occ.
__global__ void prep_kernel(const float *__restrict__ p, const float *__restrict__ X,
                            const float *__restrict__ Mm, const int *__restrict__ iobs,
                            const float *__restrict__ wprep, const float *__restrict__ bprep,
                            int nobs) {
    __shared__ float swf[64 * 16 * 4];   // [(ph*64+d)*4 + f]
    __shared__ float sbt[16 * 64];       // [ph*64 + d]
    __shared__ float red[256];
    int tid = threadIdx.x;
    for (int k = tid; k < 4096; k += 256) {
        int d = k >> 6, rem = k & 63, f = rem >> 4, ph = rem & 15;
        swf[(ph * 64 + d) * 4 + f] = wprep[k];
    }
    for (int k = tid; k < 1024; k += 256) sbt[(k & 15) * 64 + (k >> 4)] = bprep[k];
    __syncthreads();

    int d = tid & 63;
    int rbase = blockIdx.x * 8 + (tid >> 6) * 2;

    float xv[2], mean[2], var[2], err[2], msk[2];
    bool kept[2];
    float lossd = 0.0f;
#pragma unroll
    for (int i = 0; i < 2; i++) {
        int row = rbase + i;
        kept[i] = false;
        if (row < nobs) {
            int iidx = iobs[row];
            mean[i] = p[(size_t)iidx * 128 + d];
            var[i]  = fabsf(p[(size_t)iidx * 128 + 64 + d]) + 1e-6f;
            xv[i]   = X[(size_t)row * DD + d];
            msk[i]  = Mm[(size_t)row * DD + d];
            err[i]  = (xv[i] - mean[i]) * rsqrtf(var[i]);
            lossd += 0.5f * (err[i] * err[i] + logf(var[i])) * msk[i];
            kept[i] = (row == nobs - 1) || (iobs[row + 1] != iidx);
        }
    }

    __half oh[2][16];
#pragma unroll
    for (int ph = 0; ph < PH; ph++) {
        float4 wv = *reinterpret_cast<const float4 *>(&swf[(ph * 64 + d) * 4]);
        float b = sbt[ph * 64 + d];
#pragma unroll
        for (int i = 0; i < 2; i++) {
            float v = xv[i] * wv.x + mean[i] * wv.y + var[i] * wv.z + err[i] * wv.w + b;
            oh[i][ph] = __float2half_rn(fmaxf(v, 0.0f) * msk[i]);
        }
    }
#pragma unroll
    for (int i = 0; i < 2; i++) {
        if (kept[i]) {
            uint4 *src = reinterpret_cast<uint4 *>(oh[i]);
            uint4 *dst =
                reinterpret_cast<uint4 *>(&g_Ah[(size_t)(rbase + i) * KTOT + d * PH]);
            dst[0] = src[0]; dst[1] = src[1];
        }
    }

    red[tid] = lossd;
    __syncthreads();
    for (int s = 128; s > 0; s >>= 1) {
        if (tid < s) red[tid] += red[tid + s];
        __syncthreads();
    }
    if (tid == 0) g_lossPartial[blockIdx.x] = red[0];
}

// ---------- gather h rows (kept only) -> A-plane cols 1024..1535 ----------
__global__ void hconv_kernel(const float *__restrict__ h, int nobs) {
    long idx = (long)blockIdx.x * 256 + threadIdx.x;  // slot*128 + q
    int slot = (int)(idx >> 7);
    if (slot >= g_count) return;
    int q = (int)(idx & 127);
    int r = g_crow[slot];
    int hrow = g_cidx[slot];
    float4 v = *reinterpret_cast<const float4 *>(&h[(size_t)hrow * HID + q * 4]);
    __half oh[4];
    oh[0] = __float2half_rn(v.x); oh[1] = __float2half_rn(v.y);
    oh[2] = __float2half_rn(v.z); oh[3] = __float2half_rn(v.w);
    *reinterpret_cast<uint2 *>(&g_Ah[(size_t)r * KTOT + 1024 + q * 4]) =
        *reinterpret_cast<uint2 *>(oh);
}

// ---------- weights -> fp16 B-plane [1536 gates][1536 k] ----------
__global__ void wconv_kernel(const float *__restrict__ wih, const float *__restrict__ whh) {
    int idx = blockIdx.x * 256 + threadIdx.x;  // over 1536*384 float4 units
    if (idx >= KTOT * 384) return;
    int g = idx / 384, q = idx - g * 384;
    int k = q * 4;
    float4 v = (k < 1024)
                   ? *reinterpret_cast<const float4 *>(&wih[(size_t)g * 1024 + k])
                   : *reinterpret_cast<const float4 *>(&whh[(size_t)g * 512 + (k - 1024)]);
    __half o[4];
    o[0] = __float2half_rn(v.x); o[1] = __float2half_rn(v.y);
    o[2] = __float2half_rn(v.z); o[3] = __float2half_rn(v.w);
    *reinterpret_cast<uint2 *>(&g_Bh[(size_t)g * KTOT + k]) = *reinterpret_cast<uint2 *>(o);
}

// ---------- main MMA GEMM + GRU epilogue ----------
// stage (row stride 144B, conflict-free for ldmatrix: banks step 4/row):
//   A 128x144 = 18432 | B 192x144 = 27648   -> 46080/stage, 5 stages
#define A_STRIDE 144
#define SA 0
#define SB 18432
#define STAGE 46080
#define NSTAGE 5
#define GEMM_SMEM (NSTAGE * STAGE)   // 230400 <= 232448
#define NT 512                       // 16 warps = 4 per SMSP

__device__ __forceinline__ void load_chunk(int c, char *stb, const int *srows, int jb,
                                           int tid) {
    size_t kof = (size_t)c * KCH;
#pragma unroll
    for (int u = 0; u < 2; u++) {            // A: 128 rows x 8 granules of 16B
        int idx = tid + u * NT;
        int r = idx >> 3, gq = idx & 7;
        cpasync16(smem_u32(stb + SA + r * A_STRIDE + gq * 16),
                  g_Ah + (size_t)srows[r] * KTOT + kof + gq * 8);
    }
#pragma unroll
    for (int u = 0; u < 3; u++) {            // B: 192 rows x 8 granules
        int idx = tid + u * NT;
        int r = idx >> 3, gq = idx & 7;
        int grow = (r >> 6) * HID + jb + (r & 63);   // gate*512 + jb + jr
        cpasync16(smem_u32(stb + SB + r * A_STRIDE + gq * 16),
                  g_Bh + (size_t)grow * KTOT + kof + gq * 8);
    }
}

// One chunk's compute: 4 kk steps of ldsm + 12 MMAs per warp-tile.
#define COMPUTE_CHUNK(STB, ACCN)                                                   \
    do {                                                                           \
        uint32_t sb32 = smem_u32(STB);                                             \
        _Pragma("unroll")                                                          \
        for (int kk = 0; kk < 4; kk++) {                                           \
            uint32_t a[2][4];                                                      \
            ldsm_x4(a[0], sb32 + aoff + kk * 32);                                  \
            ldsm_x4(a[1], sb32 + aoff + 16 * A_STRIDE + kk * 32);                  \
            uint32_t bR[4], bZ[4], bN[4];                                          \
            ldsm_x4(bR, sb32 + boff + kk * 32);                                    \
            ldsm_x4(bZ, sb32 + boff + 64 * A_STRIDE + kk * 32);                    \
            ldsm_x4(bN, sb32 + boff + 128 * A_STRIDE + kk * 32);                   \
            _Pragma("unroll")                                                      \
            for (int mt = 0; mt < 2; mt++) {                                       \
                mma_fp16(accR[mt][0], a[mt], bR[0], bR[1]);                        \
                mma_fp16(accR[mt][1], a[mt], bR[2], bR[3]);                        \
                mma_fp16(accZ[mt][0], a[mt], bZ[0], bZ[1]);                        \
                mma_fp16(accZ[mt][1], a[mt], bZ[2], bZ[3]);                        \
                mma_fp16(ACCN[mt][0], a[mt], bN[0], bN[1]);                        \
                mma_fp16(ACCN[mt][1], a[mt], bN[2], bN[3]);                        \
            }                                                                      \
        }                                                                          \
    } while (0)

__global__ __launch_bounds__(NT, 1)
void gru_mma_kernel(const float *__restrict__ h, const float *__restrict__ bih,
                    const float *__restrict__ bhh, float *__restrict__ out) {
    extern __shared__ char smem[];
    __shared__ int srows[128];
    int tid = threadIdx.x, wid = tid >> 5, lane = tid & 31;
    int mg = wid >> 2, jg = wid & 3;          // 4 M-groups (32 rows) x 4 J-groups
    int g = lane >> 2, t = lane & 3;
    int rowbase = blockIdx.y * 128;
    int jb = blockIdx.x * 64;

    int n_keep = g_count;
    if (rowbase >= n_keep) return;

    if (tid < 128) {
        int slot = rowbase + tid;
        srows[tid] = (slot < n_keep) ? g_crow[slot] : 0;
    }
    __syncthreads();

    // ldmatrix per-lane address offsets (within a stage)
    uint32_t aoff = SA + (uint32_t)(mg * 32 + (lane & 15)) * A_STRIDE + ((lane >> 4) << 4);
    uint32_t boff = SB + (uint32_t)(jg * 16 + (lane & 7) + ((lane & 16) >> 1)) * A_STRIDE +
                    ((lane & 8) << 1);

    float accR[2][2][4] = {}, accZ[2][2][4] = {};
    float accNI[2][2][4] = {}, accNH[2][2][4] = {};

    // prologue: fill 4 of 5 stages
#pragma unroll
    for (int c = 0; c < 4; c++) {
        load_chunk(c, smem + (size_t)c * STAGE, srows, jb, tid);
        asm volatile("cp.async.commit_group;" ::: "memory");
    }

    int sidx = 0, pidx = 4;   // stage of chunk c; stage of chunk c+4
    for (int c = 0; c < 16; c++) {   // phase 1: n-gate -> accNI
        char *stb = smem + (size_t)sidx * STAGE;
        asm volatile("cp.async.wait_group 3;" ::: "memory");
        __syncthreads();
        load_chunk(c + 4, smem + (size_t)pidx * STAGE, srows, jb, tid);
        asm volatile("cp.async.commit_group;" ::: "memory");
        COMPUTE_CHUNK(stb, accNI);
        if (++sidx == NSTAGE) sidx = 0;
        if (++pidx == NSTAGE) pidx = 0;
    }
    for (int c = 16; c < NCHUNK; c++) {  // phase 2: n-gate -> accNH
        char *stb = smem + (size_t)sidx * STAGE;
        asm volatile("cp.async.wait_group 3;" ::: "memory");
        __syncthreads();
        if (c + 4 < NCHUNK)
            load_chunk(c + 4, smem + (size_t)pidx * STAGE, srows, jb, tid);
        asm volatile("cp.async.commit_group;" ::: "memory");
        COMPUTE_CHUNK(stb, accNH);
        if (++sidx == NSTAGE) sidx = 0;
        if (++pidx == NSTAGE) pidx = 0;
    }

    // ---- epilogue: GRU pointwise + scatter (all thread-local; rows distinct)
#pragma unroll
    for (int mt = 0; mt < 2; mt++) {
#pragma unroll
        for (int h2 = 0; h2 < 2; h2++) {
            int slot = rowbase + mg * 32 + mt * 16 + g + h2 * 8;
            if (slot < n_keep) {
                int hrow = g_cidx[slot];
#pragma unroll
                for (int jt = 0; jt < 2; jt++) {
#pragma unroll
                    for (int ec = 0; ec < 2; ec++) {
                        int e = h2 * 2 + ec;
                        int j = jb + jg * 16 + jt * 8 + t * 2 + ec;
                        float sr = accR[mt][jt][e] + bih[j] + bhh[j];
                        float sz = accZ[mt][jt][e] + bih[HID + j] + bhh[HID + j];
                        float si = accNI[mt][jt][e] + bih[2 * HID + j];
                        float sh = accNH[mt][jt][e] + bhh[2 * HID + j];
                        float r = 1.0f / (1.0f + expf(-sr));
                        float z = 1.0f / (1.0f + expf(-sz));
                        float n = tanhf(si + r * sh);
                        float hp = h[(size_t)hrow * HID + j];
                        out[(size_t)hrow * HID + j] = (1.0f - z) * n + z * hp;
                    }
                }
            }
        }
    }
}

// ---------- final loss reduction ----------
__global__ void loss_final_kernel(float *__restrict__ out, int nPart, long pos) {
    __shared__ float red[256];
    float s = 0.0f;
    for (int k = threadIdx.x; k < nPart; k += 256) s += g_lossPartial[k];
    red[threadIdx.x] = s;
    __syncthreads();
    for (int t = 128; t > 0; t >>= 1) {
        if (threadIdx.x < t) red[threadIdx.x] += red[threadIdx.x + t];
        __syncthreads();
    }
    if (threadIdx.x == 0) out[pos] = red[0];
}

// ---------- launch ----------
extern "C" void kernel_launch(void *const *d_in, const int *in_sizes, int n_in,
                              void *d_out, int out_size) {
    const float *h     = (const float *)d_in[0];
    const float *p     = (const float *)d_in[1];
    const float *X     = (const float *)d_in[2];
    const float *M     = (const float *)d_in[3];
    const int   *iobs  = (const int *)d_in[4];
    const float *wprep = (const float *)d_in[5];
    const float *bprep = (const float *)d_in[6];
    const float *wih   = (const float *)d_in[7];
    const float *whh   = (const float *)d_in[8];
    const float *bih   = (const float *)d_in[9];
    const float *bhh   = (const float *)d_in[10];

    int Nh = in_sizes[0] / HID;    // 100000
    int nobs = in_sizes[4];        // 50000
    float *out = (float *)d_out;

    cudaFuncSetAttribute(gru_mma_kernel, cudaFuncAttributeMaxDynamicSharedMemorySize,
                         GEMM_SMEM);

    reset_kernel<<<16, 256>>>();
    compact_kernel<<<(nobs + 255) / 256, 256>>>(iobs, nobs);

    long n4 = (long)Nh * HID / 4;
    copy_kernel<<<4096, 256>>>((float4 *)out, (const float4 *)h, n4);

    int nPrep = (nobs + 7) / 8;
    prep_kernel<<<nPrep, 256>>>(p, X, M, iobs, wprep, bprep, nobs);
    hconv_kernel<<<(int)(((long)nobs * 128 + 255) / 256), 256>>>(h, nobs);
    wconv_kernel<<<(KTOT * 384 + 255) / 256, 256>>>(wih, whh);

    dim3 grid(HID / 64, (nobs + 127) / 128);   // 8 x 391 static; g_count exit
    gru_mma_kernel<<<grid, NT, GEMM_SMEM>>>(h, bih, bhh, out);

    if ((long)out_size > (long)Nh * HID)
        loss_final_kernel<<<1, 256>>>(out, nPrep, (long)out_size - 1);
}